// round 7
// baseline (speedup 1.0000x reference)
#include <cuda_runtime.h>
#include <math.h>
#include <stdint.h>

#define NB 32
#define NT 512
#define NC 256
#define ND 1024
#define NH 16
#define NL 6
#define NFF 4096
#define NO 256
#define NQ 8
#define NK 1024
#define NTOK (NB*NT)

#define QKV_SZ  (ND*3*ND)
#define PROJ_SZ (ND*ND)
#define FF1_SZ  (ND*NFF)
#define FF2_SZ  (NFF*ND)
#define OFF_WIN 0
#define OFF_QKV (NC*ND)
#define OFF_PROJ (OFF_QKV + 6*QKV_SZ)
#define OFF_FF1  (OFF_PROJ + 6*PROJ_SZ)
#define OFF_FF2  (OFF_FF1 + 6*FF1_SZ)
#define W_TOTAL  (OFF_FF2 + 6*FF2_SZ)

#define SB_WIN  0
#define SB_QKV  1024
#define SB_PROJ (SB_QKV + 6*3*ND)
#define SB_FF1  (SB_PROJ + 6*ND)
#define SB_FF2  (SB_FF1 + 6*NFF)
#define SB_TOTAL (SB_FF2 + 6*ND)

__device__ float g_h   [(size_t)NTOK * ND];
__device__ float g_qkv [(size_t)NTOK * 3 * ND];
__device__ float g_attF[(size_t)NTOK * ND];
__device__ float g_ffF [(size_t)NTOK * NFF];
__device__ float g_last[NB * ND];
__device__ float g_z1  [NB * ND];
__device__ float g_z   [NB * NO];

__device__ __align__(16) char g_w1[W_TOTAL];
__device__ __align__(16) char g_w2[W_TOTAL];
__device__ __align__(16) char g_a1[(size_t)NTOK * ND];
__device__ __align__(16) char g_a2[(size_t)NTOK * ND];
__device__ __align__(16) char g_f1[(size_t)NTOK * NFF];
__device__ __align__(16) char g_f2[(size_t)NTOK * NFF];
__device__ __align__(16) char g_x1[(size_t)NTOK * NC];
__device__ __align__(16) char g_x2[(size_t)NTOK * NC];

__device__ int   g_sbmax[SB_TOTAL];
__device__ float g_sbf  [SB_TOTAL];
__device__ float g_sa   [NTOK];

__device__ __forceinline__ float gelu_exact(float v) {
    return 0.5f * v * (1.0f + erff(v * 0.70710678118654752f));
}
__device__ __forceinline__ void quant2(float v, float inv, char& c1, char& c2) {
    float q = fminf(127.f, fmaxf(-127.f, v * inv));
    int i1 = __float2int_rn(q);
    int i2 = __float2int_rn((q - (float)i1) * 128.f);
    c1 = (char)i1; c2 = (char)i2;
}
__device__ __forceinline__ uint32_t smem_u32(const void* p) {
    uint32_t a;
    asm("{ .reg .u64 t; cvta.to.shared.u64 t, %1; cvt.u32.u64 %0, t; }"
        : "=r"(a) : "l"(p));
    return a;
}
__device__ __forceinline__ void cp16(uint32_t dst, const void* src) {
    asm volatile("cp.async.cg.shared.global [%0], [%1], 16;"
                 :: "r"(dst), "l"(src) : "memory");
}
#define CP_COMMIT() asm volatile("cp.async.commit_group;" ::: "memory")
#define CP_WAIT2()  asm volatile("cp.async.wait_group 2;" ::: "memory")

__device__ __forceinline__ void ldsm_x4(uint32_t* r, uint32_t addr) {
    asm volatile("ldmatrix.sync.aligned.m8n8.x4.shared.b16 {%0,%1,%2,%3}, [%4];"
                 : "=r"(r[0]), "=r"(r[1]), "=r"(r[2]), "=r"(r[3]) : "r"(addr));
}
__device__ __forceinline__ void mma_s8(int* d, const uint32_t* a, const uint32_t* b) {
    asm volatile("mma.sync.aligned.m16n8k32.row.col.s32.s8.s8.s32 "
                 "{%0,%1,%2,%3}, {%4,%5,%6,%7}, {%8,%9}, {%0,%1,%2,%3};"
                 : "+r"(d[0]), "+r"(d[1]), "+r"(d[2]), "+r"(d[3])
                 : "r"(a[0]), "r"(a[1]), "r"(a[2]), "r"(a[3]),
                   "r"(b[0]), "r"(b[1]));
}

// ---------------------------------------------------------------------------
// int8 2-limb Ozaki GEMM. C = sa*sb*(S1 + S2/128 + S3/16384) + bias.
// A limbs [M,K], W pre-transposed limbs [N,K], per-row scales.
// Block 64x128, BK=64, 256 thr (8 warps 2Mx4N, warp 32x32), 3-stage cp.async.
// SMEM rows: 64B data + 16B pad = 80B stride (conflict-free ldmatrix).
// MODE 0: fp32  1: +pos[(row%NT)*N+col]  2: gelu->fp32  3: +extra residual
// ---------------------------------------------------------------------------
#define QA1 0
#define QA2 5120
#define QB1 10240
#define QB2 20480
#define QSTAGE 30720
#define QSMEM  (3*QSTAGE)   // 92160

__device__ __forceinline__ void load_stage_q(
    uint32_t sb, int c, int tid, int rowBase, int colBase, int K,
    const char* __restrict__ A1, const char* __restrict__ A2,
    const char* __restrict__ B1, const char* __restrict__ B2)
{
    size_t koff = (size_t)c * 64;
    {
        int r = tid >> 2, q = tid & 3;
        uint32_t so = (uint32_t)(r * 80 + q * 16);
        size_t src = (size_t)(rowBase + r) * K + koff + q * 16;
        cp16(sb + QA1 + so, A1 + src);
        cp16(sb + QA2 + so, A2 + src);
    }
#pragma unroll
    for (int i = 0; i < 2; i++) {
        int lin = tid + (i << 8);
        int r = lin >> 2, q = lin & 3;
        uint32_t so = (uint32_t)(r * 80 + q * 16);
        size_t src = (size_t)(colBase + r) * K + koff + q * 16;
        cp16(sb + QB1 + so, B1 + src);
        cp16(sb + QB2 + so, B2 + src);
    }
    CP_COMMIT();
}

template<int MODE>
__global__ __launch_bounds__(256)
void gemm_q(const char* __restrict__ A1, const char* __restrict__ A2,
            const char* __restrict__ B1, const char* __restrict__ B2,
            const float* __restrict__ saR, const float* __restrict__ sbC,
            const float* __restrict__ bias, const float* __restrict__ extra,
            float* __restrict__ Cf, int M, int N, int K)
{
    extern __shared__ __align__(1024) unsigned char dynsmem[];
    uint32_t sbase = smem_u32(dynsmem);
    const int tid = threadIdx.x;
    const int lane = tid & 31;
    const int warp = tid >> 5;
    const int warpM = warp & 1;
    const int warpN = warp >> 1;
    const int rowBase = blockIdx.y * 64;
    const int colBase = blockIdx.x * 128;
    const int nc = K >> 6;

    int S1[2][4][4], S2[2][4][4], S3[2][4][4];
#pragma unroll
    for (int mt = 0; mt < 2; mt++)
#pragma unroll
        for (int nt = 0; nt < 4; nt++)
#pragma unroll
            for (int e = 0; e < 4; e++) { S1[mt][nt][e]=0; S2[mt][nt][e]=0; S3[mt][nt][e]=0; }

    load_stage_q(sbase,            0, tid, rowBase, colBase, K, A1, A2, B1, B2);
    load_stage_q(sbase +   QSTAGE, 1, tid, rowBase, colBase, K, A1, A2, B1, B2);
    load_stage_q(sbase + 2*QSTAGE, 2, tid, rowBase, colBase, K, A1, A2, B1, B2);

    const int aRow = warpM * 32 + (lane & 15);
    const uint32_t aColOff = (uint32_t)((lane >> 4) * 16);
    const int bRow = warpN * 32 + ((lane >> 4) & 1) * 8 + (lane & 7);
    const uint32_t bColOff = (uint32_t)(((lane >> 3) & 1) * 16);

    int stage = 0;
    for (int c = 0; c < nc; c++) {
        CP_WAIT2();
        __syncthreads();
        uint32_t sbb = sbase + (uint32_t)stage * QSTAGE;
#pragma unroll
        for (int kk = 0; kk < 2; kk++) {
            uint32_t kb = (uint32_t)(kk * 32);
            uint32_t a1f[2][4], a2f[2][4];
#pragma unroll
            for (int mt = 0; mt < 2; mt++) {
                uint32_t ad = sbb + QA1 + (uint32_t)((aRow + mt * 16) * 80) + kb + aColOff;
                ldsm_x4(a1f[mt], ad);
                ldsm_x4(a2f[mt], ad + (QA2 - QA1));
            }
#pragma unroll
            for (int ng = 0; ng < 2; ng++) {
                uint32_t bd = sbb + QB1 + (uint32_t)((bRow + ng * 16) * 80) + kb + bColOff;
                uint32_t rb1[4], rb2[4];
                ldsm_x4(rb1, bd);
                ldsm_x4(rb2, bd + (QB2 - QB1));
#pragma unroll
                for (int mt = 0; mt < 2; mt++) {
                    mma_s8(S1[mt][2*ng],   a1f[mt], rb1);
                    mma_s8(S2[mt][2*ng],   a1f[mt], rb2);
                    mma_s8(S2[mt][2*ng],   a2f[mt], rb1);
                    mma_s8(S3[mt][2*ng],   a2f[mt], rb2);
                    mma_s8(S1[mt][2*ng+1], a1f[mt], rb1 + 2);
                    mma_s8(S2[mt][2*ng+1], a1f[mt], rb2 + 2);
                    mma_s8(S2[mt][2*ng+1], a2f[mt], rb1 + 2);
                    mma_s8(S3[mt][2*ng+1], a2f[mt], rb2 + 2);
                }
            }
        }
        __syncthreads();
        if (c + 3 < nc)
            load_stage_q(sbase + (uint32_t)stage * QSTAGE, c + 3, tid,
                         rowBase, colBase, K, A1, A2, B1, B2);
        else
            CP_COMMIT();
        stage = (stage == 2) ? 0 : stage + 1;
    }

    const float c2 = 0.0078125f, c3 = 6.103515625e-05f;
#pragma unroll
    for (int mt = 0; mt < 2; mt++) {
        int row0 = rowBase + warpM * 32 + mt * 16 + (lane >> 2);
        float sa0 = saR[row0], sa1 = saR[row0 + 8];
#pragma unroll
        for (int nt = 0; nt < 4; nt++) {
            int col = colBase + warpN * 32 + nt * 8 + (lane & 3) * 2;
            float sb0 = sbC[col], sb1 = sbC[col + 1];
            float b0 = bias[col], b1 = bias[col + 1];
#pragma unroll
            for (int half = 0; half < 2; half++) {
                int row = row0 + half * 8;
                float sav = half ? sa1 : sa0;
                int e0 = half * 2, e1 = half * 2 + 1;
                float v0 = sav * sb0 * ((float)S1[mt][nt][e0] + c2 * (float)S2[mt][nt][e0]
                         + c3 * (float)S3[mt][nt][e0]) + b0;
                float v1 = sav * sb1 * ((float)S1[mt][nt][e1] + c2 * (float)S2[mt][nt][e1]
                         + c3 * (float)S3[mt][nt][e1]) + b1;
                if (MODE == 1) {
                    size_t pr = (size_t)(row & (NT - 1)) * N + col;
                    v0 += extra[pr]; v1 += extra[pr + 1];
                }
                if (MODE == 3) {
                    size_t pr = (size_t)row * N + col;
                    v0 += extra[pr]; v1 += extra[pr + 1];
                }
                if (MODE == 2) { v0 = gelu_exact(v0); v1 = gelu_exact(v1); }
                size_t o = (size_t)row * N + col;
                Cf[o] = v0; Cf[o + 1] = v1;
            }
        }
    }
}

// ---------------- weight quantization ----------------
__global__ __launch_bounds__(256)
void sb_init(int* sbmax, int n) {
    int i = blockIdx.x * 256 + threadIdx.x;
    if (i < n) sbmax[i] = 0;
}
__global__ __launch_bounds__(256)
void colmax(const float* __restrict__ W, int* sbmax, int K, int N) {
    int n = blockIdx.x * 256 + threadIdx.x;
    int k0 = blockIdx.y * 256;
    float m = 0.f;
    for (int kk = 0; kk < 256; kk++)
        m = fmaxf(m, fabsf(W[(size_t)(k0 + kk) * N + n]));
    atomicMax(&sbmax[n], __float_as_int(m));
}
__global__ __launch_bounds__(256)
void sb_scale(const int* sbmax, float* sbf, int n) {
    int i = blockIdx.x * 256 + threadIdx.x;
    if (i < n) sbf[i] = fmaxf(__int_as_float(sbmax[i]), 1e-30f) * (1.f / 127.f);
}
__global__ __launch_bounds__(256)
void wquant(const float* __restrict__ W, char* __restrict__ o1,
            char* __restrict__ o2, const float* __restrict__ sbf, int K, int N)
{
    __shared__ float t[32][33];
    const int tx = threadIdx.x, ty = threadIdx.y;
    const int n0 = blockIdx.x * 32, k0 = blockIdx.y * 32;
#pragma unroll
    for (int i = 0; i < 4; i++)
        t[ty + 8 * i][tx] = W[(size_t)(k0 + ty + 8 * i) * N + n0 + tx];
    __syncthreads();
#pragma unroll
    for (int i = 0; i < 4; i++) {
        int n = n0 + ty + 8 * i;
        float inv = __fdividef(1.f, sbf[n]);
        char c1, c2; quant2(t[tx][ty + 8 * i], inv, c1, c2);
        size_t o = (size_t)n * K + k0 + tx;
        o1[o] = c1; o2[o] = c2;
    }
}

// ---------------- activation row quantization (D = 256/1024/4096) ----------
__global__ __launch_bounds__(256)
void rowquant(const float* __restrict__ in, char* __restrict__ q1,
              char* __restrict__ q2, float* __restrict__ sa, int D)
{
    __shared__ float red[9];
    const int row = blockIdx.x, tid = threadIdx.x;
    const int nv = D >> 8;
    float v[16];
    float mx = 1e-30f;
    for (int i = 0; i < nv; i++) {
        v[i] = in[(size_t)row * D + i * 256 + tid];
        mx = fmaxf(mx, fabsf(v[i]));
    }
#pragma unroll
    for (int o = 16; o > 0; o >>= 1)
        mx = fmaxf(mx, __shfl_xor_sync(0xffffffffu, mx, o));
    if ((tid & 31) == 0) red[tid >> 5] = mx;
    __syncthreads();
    if (tid < 32) {
        float m = (tid < 8) ? red[tid] : 0.f;
#pragma unroll
        for (int o = 4; o > 0; o >>= 1)
            m = fmaxf(m, __shfl_xor_sync(0xffffffffu, m, o));
        if (tid == 0) red[8] = m;
    }
    __syncthreads();
    float m = red[8];
    float inv = 127.f / m;
    for (int i = 0; i < nv; i++) {
        char c1, c2; quant2(v[i], inv, c1, c2);
        size_t o = (size_t)row * D + i * 256 + tid;
        q1[o] = c1; q2[o] = c2;
    }
    if (tid == 0) sa[row] = m * (1.f / 127.f);
}

// ---------------- LayerNorm: OUT=0 fp32, OUT=1 int8 2-limb ----------------
template<int OUT>
__global__ __launch_bounds__(256)
void ln_kernel(const float* __restrict__ x, const float* __restrict__ g,
               const float* __restrict__ b, float* __restrict__ yf,
               char* __restrict__ q1, char* __restrict__ q2,
               float* __restrict__ sa, size_t rowStride)
{
    __shared__ float red[20];
    const int row = blockIdx.x, tid = threadIdx.x;
    const float* xr = x + (size_t)row * rowStride;
    float4 v = ((const float4*)xr)[tid];
    float s  = v.x + v.y + v.z + v.w;
    float sq = v.x*v.x + v.y*v.y + v.z*v.z + v.w*v.w;
#pragma unroll
    for (int o = 16; o > 0; o >>= 1) {
        s  += __shfl_xor_sync(0xffffffffu, s,  o);
        sq += __shfl_xor_sync(0xffffffffu, sq, o);
    }
    if ((tid & 31) == 0) { red[tid >> 5] = s; red[8 + (tid >> 5)] = sq; }
    __syncthreads();
    if (tid < 32) {
        float ws = (tid < 8) ? red[tid]     : 0.f;
        float wq = (tid < 8) ? red[8 + tid] : 0.f;
#pragma unroll
        for (int o = 4; o > 0; o >>= 1) {
            ws += __shfl_xor_sync(0xffffffffu, ws, o);
            wq += __shfl_xor_sync(0xffffffffu, wq, o);
        }
        if (tid == 0) { red[16] = ws; red[17] = wq; }
    }
    __syncthreads();
    float mean = red[16] * (1.f / ND);
    float var  = red[17] * (1.f / ND) - mean * mean;
    float rstd = rsqrtf(var + 1e-5f);
    float4 gg = ((const float4*)g)[tid];
    float4 bb = ((const float4*)b)[tid];
    float o0 = (v.x - mean) * rstd * gg.x + bb.x;
    float o1 = (v.y - mean) * rstd * gg.y + bb.y;
    float o2 = (v.z - mean) * rstd * gg.z + bb.z;
    float o3 = (v.w - mean) * rstd * gg.w + bb.w;
    if (OUT == 0) {
        float4 o4 = {o0, o1, o2, o3};
        ((float4*)(yf + (size_t)row * ND))[tid] = o4;
    } else {
        float mx = fmaxf(fmaxf(fabsf(o0), fabsf(o1)), fmaxf(fabsf(o2), fabsf(o3)));
        mx = fmaxf(mx, 1e-30f);
#pragma unroll
        for (int o = 16; o > 0; o >>= 1)
            mx = fmaxf(mx, __shfl_xor_sync(0xffffffffu, mx, o));
        if ((tid & 31) == 0) red[tid >> 5] = mx;
        __syncthreads();
        if (tid < 32) {
            float m = (tid < 8) ? red[tid] : 0.f;
#pragma unroll
            for (int o = 4; o > 0; o >>= 1)
                m = fmaxf(m, __shfl_xor_sync(0xffffffffu, m, o));
            if (tid == 0) red[18] = m;
        }
        __syncthreads();
        float m = red[18];
        float inv = 127.f / m;
        char c[8];
        quant2(o0, inv, c[0], c[4]); quant2(o1, inv, c[1], c[5]);
        quant2(o2, inv, c[2], c[6]); quant2(o3, inv, c[3], c[7]);
        size_t base = (size_t)row * ND + tid * 4;
        *(char4*)(q1 + base) = make_char4(c[0], c[1], c[2], c[3]);
        *(char4*)(q2 + base) = make_char4(c[4], c[5], c[6], c[7]);
        if (tid == 0) sa[row] = m * (1.f / 127.f);
    }
}

// ---------------- flash attention (fp32 SIMT), fp32 out ----------------
#define AST 65
#define ATTN_SMEM (4 * 64 * AST * (int)sizeof(float))

__global__ __launch_bounds__(256)
void attn_kernel(const float* __restrict__ qkv, float* __restrict__ out)
{
    extern __shared__ __align__(1024) unsigned char dynsmem[];
    float* sm = (float*)dynsmem;
    float* sQ = sm;
    float* sK = sQ + 64 * AST;
    float* sV = sK + 64 * AST;
    float* sP = sV + 64 * AST;

    const int qt = blockIdx.x, h = blockIdx.y, b = blockIdx.z;
    const int tid = threadIdx.x;
    const int r = tid >> 2;
    const int cg = tid & 3;
    const float scale = 0.125f;

    for (int l = tid; l < 64 * 64; l += 256) {
        int m = l >> 6, d = l & 63;
        sQ[m * AST + d] =
            qkv[(size_t)(b * NT + qt * 64 + m) * (3 * ND) + h * 64 + d];
    }

    float m_run = -1e30f, l_run = 0.f;
    float accO[16];
#pragma unroll
    for (int j = 0; j < 16; j++) accO[j] = 0.f;
    const int qi = qt * 64 + r;

    for (int kt = 0; kt <= qt; kt++) {
        __syncthreads();
        for (int l = tid; l < 64 * 64; l += 256) {
            int m = l >> 6, d = l & 63;
            size_t base = (size_t)(b * NT + kt * 64 + m) * (3 * ND) + h * 64 + d;
            sK[m * AST + d] = qkv[base + ND];
            sV[m * AST + d] = qkv[base + 2 * ND];
        }
        __syncthreads();

        float s[16];
#pragma unroll
        for (int j = 0; j < 16; j++) s[j] = 0.f;
        for (int d = 0; d < 64; d++) {
            float qv = sQ[r * AST + d];
#pragma unroll
            for (int j = 0; j < 16; j++)
                s[j] += qv * sK[(cg + 4 * j) * AST + d];
        }
        float tmax = -1e30f;
#pragma unroll
        for (int j = 0; j < 16; j++) {
            int ki = kt * 64 + cg + 4 * j;
            s[j] = (ki <= qi) ? s[j] * scale : -1e30f;
            tmax = fmaxf(tmax, s[j]);
        }
        tmax = fmaxf(tmax, __shfl_xor_sync(0xffffffffu, tmax, 1));
        tmax = fmaxf(tmax, __shfl_xor_sync(0xffffffffu, tmax, 2));
        float m_new = fmaxf(m_run, tmax);
        float corr = expf(m_run - m_new);
        float lsum = 0.f;
#pragma unroll
        for (int j = 0; j < 16; j++) {
            float p = expf(s[j] - m_new);
            lsum += p;
            sP[r * AST + cg + 4 * j] = p;
        }
        lsum += __shfl_xor_sync(0xffffffffu, lsum, 1);
        lsum += __shfl_xor_sync(0xffffffffu, lsum, 2);
        l_run = l_run * corr + lsum;
        m_run = m_new;
#pragma unroll
        for (int j = 0; j < 16; j++) accO[j] *= corr;
        __syncthreads();

        for (int c = 0; c < 64; c++) {
            float p = sP[r * AST + c];
#pragma unroll
            for (int j = 0; j < 16; j++)
                accO[j] += p * sV[c * AST + cg + 4 * j];
        }
    }

    float inv = 1.f / l_run;
    size_t token = (size_t)(b * NT + qt * 64 + r);
#pragma unroll
    for (int j = 0; j < 16; j++)
        out[token * ND + h * 64 + cg + 4 * j] = accO[j] * inv;
}

// ---------------- head + RVQ ----------------
__global__ __launch_bounds__(256)
void small_gemm(const float* __restrict__ A, const float* __restrict__ W,
                const float* __restrict__ bias, float* __restrict__ out,
                int K, int N, int doGelu)
{
    __shared__ float sA[ND];
    const int row = blockIdx.x, tid = threadIdx.x;
    for (int i = tid; i < K; i += 256) sA[i] = A[(size_t)row * K + i];
    __syncthreads();
    for (int col = tid; col < N; col += 256) {
        float acc = 0.f;
        for (int k = 0; k < K; k++) acc += sA[k] * W[(size_t)k * N + col];
        acc += bias[col];
        if (doGelu) acc = gelu_exact(acc);
        out[(size_t)row * N + col] = acc;
    }
}

__global__ __launch_bounds__(256)
void rvq_kernel(const float* __restrict__ z, const float* __restrict__ codebooks,
                const float* __restrict__ layer_scales, float* __restrict__ out)
{
    __shared__ float res[NO];
    __shared__ float bestd[256];
    __shared__ int   besti[256];
    const int row = blockIdx.x, tid = threadIdx.x;
    res[tid] = z[(size_t)row * NO + tid];
    float outv = 0.f;
    for (int q = 0; q < NQ; q++) {
        __syncthreads();
        const float* cb = codebooks + (size_t)q * NK * NO;
        float bd = 1e30f; int bi = 0;
        for (int c = tid; c < NK; c += 256) {
            const float* e = cb + (size_t)c * NO;
            float dot = 0.f, nrm = 0.f;
            for (int d = 0; d < NO; d += 4) {
                float4 e4 = *(const float4*)(e + d);
                dot += res[d]*e4.x + res[d+1]*e4.y + res[d+2]*e4.z + res[d+3]*e4.w;
                nrm += e4.x*e4.x + e4.y*e4.y + e4.z*e4.z + e4.w*e4.w;
            }
            float dist = nrm - 2.f * dot;
            if (dist < bd) { bd = dist; bi = c; }
        }
        bestd[tid] = bd; besti[tid] = bi;
        __syncthreads();
        for (int sft = 128; sft > 0; sft >>= 1) {
            if (tid < sft) {
                float od = bestd[tid + sft]; int oi = besti[tid + sft];
                if (od < bestd[tid] || (od == bestd[tid] && oi < besti[tid])) {
                    bestd[tid] = od; besti[tid] = oi;
                }
            }
            __syncthreads();
        }
        int best = besti[0];
        float sig = 1.f / (1.f + expf(-layer_scales[q]));
        float ev = cb[(size_t)best * NO + tid];
        outv += sig * ev;
        res[tid] = res[tid] - ev;
    }
    out[(size_t)row * NO + tid] = outv;
}

// ---------------------------------------------------------------------------
extern "C" void kernel_launch(void* const* d_in, const int* in_sizes, int n_in,
                              void* d_out, int out_size)
{
    const float* x      = (const float*)d_in[0];
    const float* w_in   = (const float*)d_in[1];
    const float* b_in   = (const float*)d_in[2];
    const float* pos    = (const float*)d_in[3];
    const float* ln1_g  = (const float*)d_in[4];
    const float* ln1_b  = (const float*)d_in[5];
    const float* qkv_w  = (const float*)d_in[6];
    const float* qkv_b  = (const float*)d_in[7];
    const float* proj_w = (const float*)d_in[8];
    const float* proj_b = (const float*)d_in[9];
    const float* ln2_g  = (const float*)d_in[10];
    const float* ln2_b  = (const float*)d_in[11];
    const float* ff1_w  = (const float*)d_in[12];
    const float* ff1_b  = (const float*)d_in[13];
    const float* ff2_w  = (const float*)d_in[14];
    const float* ff2_b  = (const float*)d_in[15];
    const float* lnf_g  = (const float*)d_in[16];
    const float* lnf_b  = (const float*)d_in[17];
    const float* out1_w = (const float*)d_in[18];
    const float* out1_b = (const float*)d_in[19];
    const float* out2_w = (const float*)d_in[20];
    const float* out2_b = (const float*)d_in[21];
    const float* codebooks    = (const float*)d_in[22];
    const float* layer_scales = (const float*)d_in[23];

    float *h, *qkv, *attF, *ffF, *last, *z1, *z, *sbf, *sa;
    char *w1, *w2, *a1, *a2, *f1, *f2, *x1, *x2;
    int *sbmax;
    cudaGetSymbolAddress((void**)&h,    g_h);
    cudaGetSymbolAddress((void**)&qkv,  g_qkv);
    cudaGetSymbolAddress((void**)&attF, g_attF);
    cudaGetSymbolAddress((void**)&ffF,  g_ffF);
    cudaGetSymbolAddress((void**)&last, g_last);
    cudaGetSymbolAddress((void**)&z1,   g_z1);
    cudaGetSymbolAddress((void**)&z,    g_z);
    cudaGetSymbolAddress((void**)&w1,   g_w1);
    cudaGetSymbolAddress((void**)&w2,   g_w2);
    cudaGetSymbolAddress((void**)&a1,   g_a1);
    cudaGetSymbolAddress((void**)&a2,   g_a2);
    cudaGetSymbolAddress((void**)&f1,   g_f1);
    cudaGetSymbolAddress((void**)&f2,   g_f2);
    cudaGetSymbolAddress((void**)&x1,   g_x1);
    cudaGetSymbolAddress((void**)&x2,   g_x2);
    cudaGetSymbolAddress((void**)&sbmax, g_sbmax);
    cudaGetSymbolAddress((void**)&sbf,  g_sbf);
    cudaGetSymbolAddress((void**)&sa,   g_sa);

    cudaFuncSetAttribute(attn_kernel, cudaFuncAttributeMaxDynamicSharedMemorySize, ATTN_SMEM);
    cudaFuncSetAttribute(gemm_q<0>, cudaFuncAttributeMaxDynamicSharedMemorySize, QSMEM);
    cudaFuncSetAttribute(gemm_q<1>, cudaFuncAttributeMaxDynamicSharedMemorySize, QSMEM);
    cudaFuncSetAttribute(gemm_q<2>, cudaFuncAttributeMaxDynamicSharedMemorySize, QSMEM);
    cudaFuncSetAttribute(gemm_q<3>, cudaFuncAttributeMaxDynamicSharedMemorySize, QSMEM);

    const dim3 thr(256);
    const dim3 tthr(32, 8);

    // ---- weight quantization ----
    sb_init<<<(SB_TOTAL + 255) / 256, thr>>>(sbmax, SB_TOTAL);
    colmax<<<dim3(ND/256, NC/256), thr>>>(w_in, sbmax + SB_WIN, NC, ND);
    for (int l = 0; l < NL; l++) {
        colmax<<<dim3(3*ND/256, ND/256), thr>>>(qkv_w + (size_t)l*QKV_SZ, sbmax + SB_QKV + l*3*ND, ND, 3*ND);
        colmax<<<dim3(ND/256, ND/256), thr>>>(proj_w + (size_t)l*PROJ_SZ, sbmax + SB_PROJ + l*ND, ND, ND);
        colmax<<<dim3(NFF/256, ND/256), thr>>>(ff1_w + (size_t)l*FF1_SZ, sbmax + SB_FF1 + l*NFF, ND, NFF);
        colmax<<<dim3(ND/256, NFF/256), thr>>>(ff2_w + (size_t)l*FF2_SZ, sbmax + SB_FF2 + l*ND, NFF, ND);
    }
    sb_scale<<<(SB_TOTAL + 255) / 256, thr>>>(sbmax, sbf, SB_TOTAL);
    wquant<<<dim3(ND/32, NC/32), tthr>>>(w_in, w1 + OFF_WIN, w2 + OFF_WIN, sbf + SB_WIN, NC, ND);
    for (int l = 0; l < NL; l++) {
        wquant<<<dim3(3*ND/32, ND/32), tthr>>>(qkv_w + (size_t)l*QKV_SZ,
            w1 + OFF_QKV + (size_t)l*QKV_SZ, w2 + OFF_QKV + (size_t)l*QKV_SZ, sbf + SB_QKV + l*3*ND, ND, 3*ND);
        wquant<<<dim3(ND/32, ND/32), tthr>>>(proj_w + (size_t)l*PROJ_SZ,
            w1 + OFF_PROJ + (size_t)l*PROJ_SZ, w2 + OFF_PROJ + (size_t)l*PROJ_SZ, sbf + SB_PROJ + l*ND, ND, ND);
        wquant<<<dim3(NFF/32, ND/32), tthr>>>(ff1_w + (size_t)l*FF1_SZ,
            w1 + OFF_FF1 + (size_t)l*FF1_SZ, w2 + OFF_FF1 + (size_t)l*FF1_SZ, sbf + SB_FF1 + l*NFF, ND, NFF);
        wquant<<<dim3(ND/32, NFF/32), tthr>>>(ff2_w + (size_t)l*FF2_SZ,
            w1 + OFF_FF2 + (size_t)l*FF2_SZ, w2 + OFF_FF2 + (size_t)l*FF2_SZ, sbf + SB_FF2 + l*ND, NFF, ND);
    }

    // ---- input embed: h = x @ w_in + b_in + pos ----
    rowquant<<<NTOK, thr>>>(x, x1, x2, sa, NC);
    gemm_q<1><<<dim3(ND/128, NTOK/64), thr, QSMEM>>>(
        x1, x2, w1 + OFF_WIN, w2 + OFF_WIN, sa, sbf + SB_WIN, b_in, pos,
        h, NTOK, ND, NC);

    for (int l = 0; l < NL; l++) {
        ln_kernel<1><<<NTOK, thr>>>(h, ln1_g + (size_t)l*ND, ln1_b + (size_t)l*ND,
                                    nullptr, a1, a2, sa, ND);
        gemm_q<0><<<dim3(3*ND/128, NTOK/64), thr, QSMEM>>>(
            a1, a2, w1 + OFF_QKV + (size_t)l*QKV_SZ, w2 + OFF_QKV + (size_t)l*QKV_SZ,
            sa, sbf + SB_QKV + l*3*ND, qkv_b + (size_t)l*3*ND, nullptr,
            qkv, NTOK, 3*ND, ND);
        attn_kernel<<<dim3(NT/64, NH, NB), thr, ATTN_SMEM>>>(qkv, attF);
        rowquant<<<NTOK, thr>>>(attF, a1, a2, sa, ND);
        gemm_q<3><<<dim3(ND/128, NTOK/64), thr, QSMEM>>>(
            a1, a2, w1 + OFF_PROJ + (size_t)l*PROJ_SZ, w2 + OFF_PROJ + (size_t)l*PROJ_SZ,
            sa, sbf + SB_PROJ + l*ND, proj_b + (size_t)l*ND, h,
            h, NTOK, ND, ND);
        ln_kernel<1><<<NTOK, thr>>>(h, ln2_g + (size_t)l*ND, ln2_b + (size_t)l*ND,
                                    nullptr, a1, a2, sa, ND);
        gemm_q<2><<<dim3(NFF/128, NTOK/64), thr, QSMEM>>>(
            a1, a2, w1 + OFF_FF1 + (size_t)l*FF1_SZ, w2 + OFF_FF1 + (size_t)l*FF1_SZ,
            sa, sbf + SB_FF1 + l*NFF, ff1_b + (size_t)l*NFF, nullptr,
            ffF, NTOK, NFF, ND);
        rowquant<<<NTOK, thr>>>(ffF, f1, f2, sa, NFF);
        gemm_q<3><<<dim3(ND/128, NTOK/64), thr, QSMEM>>>(
            f1, f2, w1 + OFF_FF2 + (size_t)l*FF2_SZ, w2 + OFF_FF2 + (size_t)l*FF2_SZ,
            sa, sbf + SB_FF2 + l*ND, ff2_b + (size_t)l*ND, h,
            h, NTOK, ND, NFF);
    }

    // ---- head ----
    ln_kernel<0><<<NB, thr>>>(h + (size_t)(NT - 1) * ND, lnf_g, lnf_b,
                              last, nullptr, nullptr, nullptr, (size_t)NT * ND);
    small_gemm<<<NB, thr>>>(last, out1_w, out1_b, z1, ND, ND, 1);
    small_gemm<<<NB, thr>>>(z1, out2_w, out2_b, z, ND, NO, 0);
    rvq_kernel<<<NB, thr>>>(z, codebooks, layer_scales, (float*)d_out);
}

// round 8
// speedup vs baseline: 3.7154x; 3.7154x over previous
#include <cuda_runtime.h>
#include <cuda_fp16.h>
#include <math.h>
#include <stdint.h>

#define NB 32
#define NT 512
#define NC 256
#define ND 1024
#define NH 16
#define NL 6
#define NFF 4096
#define NO 256
#define NQ 8
#define NK 1024
#define NTOK (NB*NT)

#define QKV_SZ  (ND*3*ND)
#define PROJ_SZ (ND*ND)
#define FF1_SZ  (ND*NFF)
#define FF2_SZ  (NFF*ND)
#define OFF_WIN 0
#define OFF_QKV (NC*ND)
#define OFF_PROJ (OFF_QKV + 6*QKV_SZ)
#define OFF_FF1  (OFF_PROJ + 6*PROJ_SZ)
#define OFF_FF2  (OFF_FF1 + 6*FF1_SZ)
#define W_TOTAL  (OFF_FF2 + 6*FF2_SZ)

__device__ float g_h  [(size_t)NTOK * ND];
__device__ float g_qkv[(size_t)NTOK * 3 * ND];
__device__ float g_last[NB * ND];
__device__ float g_z1  [NB * ND];
__device__ float g_z   [NB * NO];

__device__ __half g_whi[W_TOTAL];
__device__ __half g_wlo[W_TOTAL];
__device__ __half g_af [(size_t)NTOK * ND];     // activation fp16 (single plane)
__device__ __half g_ff [(size_t)NTOK * NFF];
__device__ __half g_xf [(size_t)NTOK * NC];

__device__ __forceinline__ float gelu_exact(float v) {
    return 0.5f * v * (1.0f + erff(v * 0.70710678118654752f));
}
__device__ __forceinline__ void split_h(float v, __half& h, __half& l) {
    h = __float2half(v);
    l = __float2half(v - __half2float(h));
}
__device__ __forceinline__ uint32_t smem_u32(const void* p) {
    uint32_t a;
    asm("{ .reg .u64 t; cvta.to.shared.u64 t, %1; cvt.u32.u64 %0, t; }"
        : "=r"(a) : "l"(p));
    return a;
}
__device__ __forceinline__ void cp16(uint32_t dst, const void* src) {
    asm volatile("cp.async.cg.shared.global [%0], [%1], 16;"
                 :: "r"(dst), "l"(src) : "memory");
}
#define CP_COMMIT() asm volatile("cp.async.commit_group;" ::: "memory")
#define CP_WAIT1()  asm volatile("cp.async.wait_group 1;" ::: "memory")
#define CP_WAIT0()  asm volatile("cp.async.wait_group 0;" ::: "memory")

__device__ __forceinline__ void ldsm_x4(uint32_t* r, uint32_t addr) {
    asm volatile("ldmatrix.sync.aligned.m8n8.x4.shared.b16 {%0,%1,%2,%3}, [%4];"
                 : "=r"(r[0]), "=r"(r[1]), "=r"(r[2]), "=r"(r[3]) : "r"(addr));
}
__device__ __forceinline__ void mma_f16(float* d, const uint32_t* a, const uint32_t* b) {
    asm volatile("mma.sync.aligned.m16n8k16.row.col.f32.f16.f16.f32 "
                 "{%0,%1,%2,%3}, {%4,%5,%6,%7}, {%8,%9}, {%0,%1,%2,%3};"
                 : "+f"(d[0]), "+f"(d[1]), "+f"(d[2]), "+f"(d[3])
                 : "r"(a[0]), "r"(a[1]), "r"(a[2]), "r"(a[3]),
                   "r"(b[0]), "r"(b[1]));
}

// ---------------------------------------------------------------------------
// fp16 2-pass GEMM. C[M,N] = A[M,K] @ W[K,N].
// A single fp16 [M,K]; W pre-transposed 2-limb fp16 [N,K] (Whi + Wlo).
// Acc = A*Whi + A*Wlo (fp32 accum). Block 128x128, BK=32, 256 thr
// (8 warps 2Mx4N, warp 64x32), 2-stage cp.async. Rows: 64B + 16B pad = 80B.
// MODE 0: fp32+bias  1: +pos[(row%NT)*N+col]  2: gelu->fp16  3: +extra resid
// ---------------------------------------------------------------------------
#define MT_B   10240              // 128 rows * 80B
#define STG_B  (3*MT_B)           // A, Bhi, Blo
#define GSMEM  (2*STG_B)          // 61440

__device__ __forceinline__ void load_stage(
    uint32_t sb, int c, int tid, int rowBase, int colBase, int K,
    const __half* __restrict__ A, const __half* __restrict__ Bhi,
    const __half* __restrict__ Blo)
{
    size_t koff = (size_t)c * 32;
#pragma unroll
    for (int i = 0; i < 2; i++) {
        int lin = tid + (i << 8);
        int r = lin >> 2, q = lin & 3;
        uint32_t so = (uint32_t)(r * 80 + q * 16);
        size_t srcA = (size_t)(rowBase + r) * K + koff + q * 8;
        size_t srcB = (size_t)(colBase + r) * K + koff + q * 8;
        cp16(sb + so,            A   + srcA);
        cp16(sb + MT_B + so,     Bhi + srcB);
        cp16(sb + 2 * MT_B + so, Blo + srcB);
    }
    CP_COMMIT();
}

template<int MODE>
__global__ __launch_bounds__(256)
void gemm_mma(const __half* __restrict__ A, const __half* __restrict__ Bhi,
              const __half* __restrict__ Blo, const float* __restrict__ bias,
              const float* __restrict__ extra, float* __restrict__ Cf,
              __half* __restrict__ Ch, int M, int N, int K)
{
    extern __shared__ __align__(1024) unsigned char dynsmem[];
    uint32_t sbase = smem_u32(dynsmem);
    const int tid = threadIdx.x;
    const int lane = tid & 31;
    const int warp = tid >> 5;
    const int warpM = warp & 1;
    const int warpN = warp >> 1;
    const int rowBase = blockIdx.y * 128;
    const int colBase = blockIdx.x * 128;
    const int nc = K >> 5;

    float acc[4][4][4];
#pragma unroll
    for (int mt = 0; mt < 4; mt++)
#pragma unroll
        for (int nt = 0; nt < 4; nt++)
#pragma unroll
            for (int e = 0; e < 4; e++) acc[mt][nt][e] = 0.f;

    load_stage(sbase,         0, tid, rowBase, colBase, K, A, Bhi, Blo);
    load_stage(sbase + STG_B, 1, tid, rowBase, colBase, K, A, Bhi, Blo);

    const int aRow = warpM * 64 + (lane & 15);
    const uint32_t aColOff = (uint32_t)((lane >> 4) * 16);
    const int bRow = warpN * 32 + ((lane >> 4) & 1) * 8 + (lane & 7);
    const uint32_t bColOff = (uint32_t)(((lane >> 3) & 1) * 16);

    for (int c = 0; c < nc; c++) {
        if (c + 1 < nc) { CP_WAIT1(); } else { CP_WAIT0(); }
        __syncthreads();
        uint32_t sb = sbase + (uint32_t)(c & 1) * STG_B;

#pragma unroll
        for (int kk = 0; kk < 2; kk++) {
            uint32_t kb = (uint32_t)(kk * 32);
            uint32_t ah[4][4];
#pragma unroll
            for (int mt = 0; mt < 4; mt++)
                ldsm_x4(ah[mt], sb + (uint32_t)((aRow + mt * 16) * 80) + kb + aColOff);
            uint32_t rh[4], rl[4];
            {
                uint32_t baddr = sb + MT_B + (uint32_t)(bRow * 80) + kb + bColOff;
                ldsm_x4(rh, baddr);
                ldsm_x4(rl, baddr + MT_B);
            }
            uint32_t bh0[2] = {rh[0], rh[1]}, bh1[2] = {rh[2], rh[3]};
            uint32_t bl0[2] = {rl[0], rl[1]}, bl1[2] = {rl[2], rl[3]};
            // second 16-n group for this warp (bRow+16)
            uint32_t rh2[4], rl2[4];
            {
                uint32_t baddr = sb + MT_B + (uint32_t)((bRow + 16) * 80) + kb + bColOff;
                ldsm_x4(rh2, baddr);
                ldsm_x4(rl2, baddr + MT_B);
            }
            uint32_t bh2[2] = {rh2[0], rh2[1]}, bh3[2] = {rh2[2], rh2[3]};
            uint32_t bl2[2] = {rl2[0], rl2[1]}, bl3[2] = {rl2[2], rl2[3]};
#pragma unroll
            for (int mt = 0; mt < 4; mt++) {
                mma_f16(acc[mt][0], ah[mt], bh0);
                mma_f16(acc[mt][0], ah[mt], bl0);
                mma_f16(acc[mt][1], ah[mt], bh1);
                mma_f16(acc[mt][1], ah[mt], bl1);
                mma_f16(acc[mt][2], ah[mt], bh2);
                mma_f16(acc[mt][2], ah[mt], bl2);
                mma_f16(acc[mt][3], ah[mt], bh3);
                mma_f16(acc[mt][3], ah[mt], bl3);
            }
        }
        __syncthreads();
        if (c + 2 < nc)
            load_stage(sbase + (uint32_t)(c & 1) * STG_B, c + 2, tid,
                       rowBase, colBase, K, A, Bhi, Blo);
    }

#pragma unroll
    for (int mt = 0; mt < 4; mt++) {
        int row0 = rowBase + warpM * 64 + mt * 16 + (lane >> 2);
#pragma unroll
        for (int nt = 0; nt < 4; nt++) {
            int col = colBase + warpN * 32 + nt * 8 + (lane & 3) * 2;
            float b0 = bias[col], b1 = bias[col + 1];
#pragma unroll
            for (int half = 0; half < 2; half++) {
                int row = row0 + half * 8;
                float v0 = acc[mt][nt][half * 2 + 0] + b0;
                float v1 = acc[mt][nt][half * 2 + 1] + b1;
                if (MODE == 1) {
                    size_t pr = (size_t)(row & (NT - 1)) * N + col;
                    v0 += extra[pr]; v1 += extra[pr + 1];
                }
                if (MODE == 3) {
                    size_t pr = (size_t)row * N + col;
                    v0 += extra[pr]; v1 += extra[pr + 1];
                }
                size_t o = (size_t)row * N + col;
                if (MODE == 2) {
                    v0 = gelu_exact(v0); v1 = gelu_exact(v1);
                    *(__half2*)(Ch + o) = __half2(__float2half(v0), __float2half(v1));
                } else {
                    Cf[o] = v0; Cf[o + 1] = v1;
                }
            }
        }
    }
}

// ---------------- weight transpose + fp16 2-limb split ----------------
__global__ __launch_bounds__(256)
void tsplit(const float* __restrict__ W, __half* __restrict__ oh,
            __half* __restrict__ ol, int K, int N)
{
    __shared__ float t[32][33];
    const int tx = threadIdx.x, ty = threadIdx.y;
    const int n0 = blockIdx.x * 32, k0 = blockIdx.y * 32;
#pragma unroll
    for (int i = 0; i < 4; i++)
        t[ty + 8 * i][tx] = W[(size_t)(k0 + ty + 8 * i) * N + n0 + tx];
    __syncthreads();
#pragma unroll
    for (int i = 0; i < 4; i++) {
        __half h, l; split_h(t[tx][ty + 8 * i], h, l);
        size_t o = (size_t)(n0 + ty + 8 * i) * K + k0 + tx;
        oh[o] = h; ol[o] = l;
    }
}

__global__ __launch_bounds__(256)
void xcvt(const float* __restrict__ x, __half* __restrict__ xf, int n) {
    int i = blockIdx.x * 256 + threadIdx.x;
    if (i < n) xf[i] = __float2half(x[i]);
}

// ---------------- LayerNorm: OUT=0 fp32, OUT=1 fp16 ----------------
template<int OUT>
__global__ __launch_bounds__(256)
void ln_kernel(const float* __restrict__ x, const float* __restrict__ g,
               const float* __restrict__ b, float* __restrict__ yf,
               __half* __restrict__ yh, size_t rowStride)
{
    __shared__ float red[18];
    const int row = blockIdx.x, tid = threadIdx.x;
    const float* xr = x + (size_t)row * rowStride;
    float4 v = ((const float4*)xr)[tid];
    float s  = v.x + v.y + v.z + v.w;
    float sq = v.x*v.x + v.y*v.y + v.z*v.z + v.w*v.w;
#pragma unroll
    for (int o = 16; o > 0; o >>= 1) {
        s  += __shfl_xor_sync(0xffffffffu, s,  o);
        sq += __shfl_xor_sync(0xffffffffu, sq, o);
    }
    if ((tid & 31) == 0) { red[tid >> 5] = s; red[8 + (tid >> 5)] = sq; }
    __syncthreads();
    if (tid < 32) {
        float ws = (tid < 8) ? red[tid]     : 0.f;
        float wq = (tid < 8) ? red[8 + tid] : 0.f;
#pragma unroll
        for (int o = 4; o > 0; o >>= 1) {
            ws += __shfl_xor_sync(0xffffffffu, ws, o);
            wq += __shfl_xor_sync(0xffffffffu, wq, o);
        }
        if (tid == 0) { red[16] = ws; red[17] = wq; }
    }
    __syncthreads();
    float mean = red[16] * (1.f / ND);
    float var  = red[17] * (1.f / ND) - mean * mean;
    float rstd = rsqrtf(var + 1e-5f);
    float4 gg = ((const float4*)g)[tid];
    float4 bb = ((const float4*)b)[tid];
    float o0 = (v.x - mean) * rstd * gg.x + bb.x;
    float o1 = (v.y - mean) * rstd * gg.y + bb.y;
    float o2 = (v.z - mean) * rstd * gg.z + bb.z;
    float o3 = (v.w - mean) * rstd * gg.w + bb.w;
    if (OUT == 0) {
        float4 o4 = {o0, o1, o2, o3};
        ((float4*)(yf + (size_t)row * ND))[tid] = o4;
    } else {
        size_t base = (size_t)row * ND + tid * 4;
        *(__half2*)(yh + base)     = __half2(__float2half(o0), __float2half(o1));
        *(__half2*)(yh + base + 2) = __half2(__float2half(o2), __float2half(o3));
    }
}

// ---------------- flash attention (fp32 SIMT), fp16 out ----------------
#define AST 65
#define ATTN_SMEM (4 * 64 * AST * (int)sizeof(float))

__global__ __launch_bounds__(256)
void attn_kernel(const float* __restrict__ qkv, __half* __restrict__ oh)
{
    extern __shared__ __align__(1024) unsigned char dynsmem[];
    float* sm = (float*)dynsmem;
    float* sQ = sm;
    float* sK = sQ + 64 * AST;
    float* sV = sK + 64 * AST;
    float* sP = sV + 64 * AST;

    const int qt = blockIdx.x, h = blockIdx.y, b = blockIdx.z;
    const int tid = threadIdx.x;
    const int r = tid >> 2;
    const int cg = tid & 3;
    const float scale = 0.125f;

    for (int l = tid; l < 64 * 64; l += 256) {
        int m = l >> 6, d = l & 63;
        sQ[m * AST + d] =
            qkv[(size_t)(b * NT + qt * 64 + m) * (3 * ND) + h * 64 + d];
    }

    float m_run = -1e30f, l_run = 0.f;
    float accO[16];
#pragma unroll
    for (int j = 0; j < 16; j++) accO[j] = 0.f;
    const int qi = qt * 64 + r;

    for (int kt = 0; kt <= qt; kt++) {
        __syncthreads();
        for (int l = tid; l < 64 * 64; l += 256) {
            int m = l >> 6, d = l & 63;
            size_t base = (size_t)(b * NT + kt * 64 + m) * (3 * ND) + h * 64 + d;
            sK[m * AST + d] = qkv[base + ND];
            sV[m * AST + d] = qkv[base + 2 * ND];
        }
        __syncthreads();

        float s[16];
#pragma unroll
        for (int j = 0; j < 16; j++) s[j] = 0.f;
        for (int d = 0; d < 64; d++) {
            float qv = sQ[r * AST + d];
#pragma unroll
            for (int j = 0; j < 16; j++)
                s[j] += qv * sK[(cg + 4 * j) * AST + d];
        }
        float tmax = -1e30f;
#pragma unroll
        for (int j = 0; j < 16; j++) {
            int ki = kt * 64 + cg + 4 * j;
            s[j] = (ki <= qi) ? s[j] * scale : -1e30f;
            tmax = fmaxf(tmax, s[j]);
        }
        tmax = fmaxf(tmax, __shfl_xor_sync(0xffffffffu, tmax, 1));
        tmax = fmaxf(tmax, __shfl_xor_sync(0xffffffffu, tmax, 2));
        float m_new = fmaxf(m_run, tmax);
        float corr = expf(m_run - m_new);
        float lsum = 0.f;
#pragma unroll
        for (int j = 0; j < 16; j++) {
            float p = expf(s[j] - m_new);
            lsum += p;
            sP[r * AST + cg + 4 * j] = p;
        }
        lsum += __shfl_xor_sync(0xffffffffu, lsum, 1);
        lsum += __shfl_xor_sync(0xffffffffu, lsum, 2);
        l_run = l_run * corr + lsum;
        m_run = m_new;
#pragma unroll
        for (int j = 0; j < 16; j++) accO[j] *= corr;
        __syncthreads();

        for (int c = 0; c < 64; c++) {
            float p = sP[r * AST + c];
#pragma unroll
            for (int j = 0; j < 16; j++)
                accO[j] += p * sV[c * AST + cg + 4 * j];
        }
    }

    float inv = 1.f / l_run;
    size_t token = (size_t)(b * NT + qt * 64 + r);
#pragma unroll
    for (int j = 0; j < 16; j++)
        oh[token * ND + h * 64 + cg + 4 * j] = __float2half(accO[j] * inv);
}

// ---------------- head + RVQ ----------------
__global__ __launch_bounds__(256)
void small_gemm(const float* __restrict__ A, const float* __restrict__ W,
                const float* __restrict__ bias, float* __restrict__ out,
                int K, int N, int doGelu)
{
    __shared__ float sA[ND];
    const int row = blockIdx.x, tid = threadIdx.x;
    for (int i = tid; i < K; i += 256) sA[i] = A[(size_t)row * K + i];
    __syncthreads();
    for (int col = tid; col < N; col += 256) {
        float acc = 0.f;
        for (int k = 0; k < K; k++) acc += sA[k] * W[(size_t)k * N + col];
        acc += bias[col];
        if (doGelu) acc = gelu_exact(acc);
        out[(size_t)row * N + col] = acc;
    }
}

__global__ __launch_bounds__(256)
void rvq_kernel(const float* __restrict__ z, const float* __restrict__ codebooks,
                const float* __restrict__ layer_scales, float* __restrict__ out)
{
    __shared__ float res[NO];
    __shared__ float bestd[256];
    __shared__ int   besti[256];
    const int row = blockIdx.x, tid = threadIdx.x;
    res[tid] = z[(size_t)row * NO + tid];
    float outv = 0.f;
    for (int q = 0; q < NQ; q++) {
        __syncthreads();
        const float* cb = codebooks + (size_t)q * NK * NO;
        float bd = 1e30f; int bi = 0;
        for (int c = tid; c < NK; c += 256) {
            const float* e = cb + (size_t)c * NO;
            float dot = 0.f, nrm = 0.f;
            for (int d = 0; d < NO; d += 4) {
                float4 e4 = *(const float4*)(e + d);
                dot += res[d]*e4.x + res[d+1]*e4.y + res[d+2]*e4.z + res[d+3]*e4.w;
                nrm += e4.x*e4.x + e4.y*e4.y + e4.z*e4.z + e4.w*e4.w;
            }
            float dist = nrm - 2.f * dot;
            if (dist < bd) { bd = dist; bi = c; }
        }
        bestd[tid] = bd; besti[tid] = bi;
        __syncthreads();
        for (int sft = 128; sft > 0; sft >>= 1) {
            if (tid < sft) {
                float od = bestd[tid + sft]; int oi = besti[tid + sft];
                if (od < bestd[tid] || (od == bestd[tid] && oi < besti[tid])) {
                    bestd[tid] = od; besti[tid] = oi;
                }
            }
            __syncthreads();
        }
        int best = besti[0];
        float sig = 1.f / (1.f + expf(-layer_scales[q]));
        float ev = cb[(size_t)best * NO + tid];
        outv += sig * ev;
        res[tid] = res[tid] - ev;
    }
    out[(size_t)row * NO + tid] = outv;
}

// ---------------------------------------------------------------------------
extern "C" void kernel_launch(void* const* d_in, const int* in_sizes, int n_in,
                              void* d_out, int out_size)
{
    const float* x      = (const float*)d_in[0];
    const float* w_in   = (const float*)d_in[1];
    const float* b_in   = (const float*)d_in[2];
    const float* pos    = (const float*)d_in[3];
    const float* ln1_g  = (const float*)d_in[4];
    const float* ln1_b  = (const float*)d_in[5];
    const float* qkv_w  = (const float*)d_in[6];
    const float* qkv_b  = (const float*)d_in[7];
    const float* proj_w = (const float*)d_in[8];
    const float* proj_b = (const float*)d_in[9];
    const float* ln2_g  = (const float*)d_in[10];
    const float* ln2_b  = (const float*)d_in[11];
    const float* ff1_w  = (const float*)d_in[12];
    const float* ff1_b  = (const float*)d_in[13];
    const float* ff2_w  = (const float*)d_in[14];
    const float* ff2_b  = (const float*)d_in[15];
    const float* lnf_g  = (const float*)d_in[16];
    const float* lnf_b  = (const float*)d_in[17];
    const float* out1_w = (const float*)d_in[18];
    const float* out1_b = (const float*)d_in[19];
    const float* out2_w = (const float*)d_in[20];
    const float* out2_b = (const float*)d_in[21];
    const float* codebooks    = (const float*)d_in[22];
    const float* layer_scales = (const float*)d_in[23];

    float *h, *qkv, *last, *z1, *z;
    __half *whi, *wlo, *af, *ff, *xf;
    cudaGetSymbolAddress((void**)&h,    g_h);
    cudaGetSymbolAddress((void**)&qkv,  g_qkv);
    cudaGetSymbolAddress((void**)&last, g_last);
    cudaGetSymbolAddress((void**)&z1,   g_z1);
    cudaGetSymbolAddress((void**)&z,    g_z);
    cudaGetSymbolAddress((void**)&whi,  g_whi);
    cudaGetSymbolAddress((void**)&wlo,  g_wlo);
    cudaGetSymbolAddress((void**)&af,   g_af);
    cudaGetSymbolAddress((void**)&ff,   g_ff);
    cudaGetSymbolAddress((void**)&xf,   g_xf);

    cudaFuncSetAttribute(attn_kernel, cudaFuncAttributeMaxDynamicSharedMemorySize, ATTN_SMEM);
    cudaFuncSetAttribute(gemm_mma<0>, cudaFuncAttributeMaxDynamicSharedMemorySize, GSMEM);
    cudaFuncSetAttribute(gemm_mma<1>, cudaFuncAttributeMaxDynamicSharedMemorySize, GSMEM);
    cudaFuncSetAttribute(gemm_mma<2>, cudaFuncAttributeMaxDynamicSharedMemorySize, GSMEM);
    cudaFuncSetAttribute(gemm_mma<3>, cudaFuncAttributeMaxDynamicSharedMemorySize, GSMEM);

    const dim3 thr(256);
    const dim3 tthr(32, 8);

    // ---- conversions ----
    xcvt<<<(NTOK * NC + 255) / 256, thr>>>(x, xf, NTOK * NC);
    tsplit<<<dim3(ND/32, NC/32), tthr>>>(w_in, whi + OFF_WIN, wlo + OFF_WIN, NC, ND);
    for (int l = 0; l < NL; l++) {
        tsplit<<<dim3(3*ND/32, ND/32), tthr>>>(qkv_w + (size_t)l*QKV_SZ,
            whi + OFF_QKV + (size_t)l*QKV_SZ, wlo + OFF_QKV + (size_t)l*QKV_SZ, ND, 3*ND);
        tsplit<<<dim3(ND/32, ND/32), tthr>>>(proj_w + (size_t)l*PROJ_SZ,
            whi + OFF_PROJ + (size_t)l*PROJ_SZ, wlo + OFF_PROJ + (size_t)l*PROJ_SZ, ND, ND);
        tsplit<<<dim3(NFF/32, ND/32), tthr>>>(ff1_w + (size_t)l*FF1_SZ,
            whi + OFF_FF1 + (size_t)l*FF1_SZ, wlo + OFF_FF1 + (size_t)l*FF1_SZ, ND, NFF);
        tsplit<<<dim3(ND/32, NFF/32), tthr>>>(ff2_w + (size_t)l*FF2_SZ,
            whi + OFF_FF2 + (size_t)l*FF2_SZ, wlo + OFF_FF2 + (size_t)l*FF2_SZ, NFF, ND);
    }

    // ---- h = x @ w_in + b_in + pos ----
    gemm_mma<1><<<dim3(ND/128, NTOK/128), thr, GSMEM>>>(
        xf, whi + OFF_WIN, wlo + OFF_WIN, b_in, pos, h, nullptr, NTOK, ND, NC);

    for (int l = 0; l < NL; l++) {
        ln_kernel<1><<<NTOK, thr>>>(h, ln1_g + (size_t)l*ND, ln1_b + (size_t)l*ND,
                                    nullptr, af, ND);
        gemm_mma<0><<<dim3(3*ND/128, NTOK/128), thr, GSMEM>>>(
            af, whi + OFF_QKV + (size_t)l*QKV_SZ, wlo + OFF_QKV + (size_t)l*QKV_SZ,
            qkv_b + (size_t)l*3*ND, nullptr, qkv, nullptr, NTOK, 3*ND, ND);
        attn_kernel<<<dim3(NT/64, NH, NB), thr, ATTN_SMEM>>>(qkv, af);
        gemm_mma<3><<<dim3(ND/128, NTOK/128), thr, GSMEM>>>(
            af, whi + OFF_PROJ + (size_t)l*PROJ_SZ, wlo + OFF_PROJ + (size_t)l*PROJ_SZ,
            proj_b + (size_t)l*ND, h, h, nullptr, NTOK, ND, ND);
        ln_kernel<1><<<NTOK, thr>>>(h, ln2_g + (size_t)l*ND, ln2_b + (size_t)l*ND,
                                    nullptr, af, ND);
        gemm_mma<2><<<dim3(NFF/128, NTOK/128), thr, GSMEM>>>(
            af, whi + OFF_FF1 + (size_t)l*FF1_SZ, wlo + OFF_FF1 + (size_t)l*FF1_SZ,
            ff1_b + (size_t)l*NFF, nullptr, nullptr, ff, NTOK, NFF, ND);
        gemm_mma<3><<<dim3(ND/128, NTOK/128), thr, GSMEM>>>(
            ff, whi + OFF_FF2 + (size_t)l*FF2_SZ, wlo + OFF_FF2 + (size_t)l*FF2_SZ,
            ff2_b + (size_t)l*ND, h, h, nullptr, NTOK, ND, NFF);
    }

    // ---- head ----
    ln_kernel<0><<<NB, thr>>>(h + (size_t)(NT - 1) * ND, lnf_g, lnf_b,
                              last, nullptr, (size_t)NT * ND);
    small_gemm<<<NB, thr>>>(last, out1_w, out1_b, z1, ND, ND, 1);
    small_gemm<<<NB, thr>>>(z1, out2_w, out2_b, z, ND, NO, 0);
    rvq_kernel<<<NB, thr>>>(z, codebooks, layer_scales, (float*)d_out);
}

// round 9
// speedup vs baseline: 4.6022x; 1.2387x over previous
#include <cuda_runtime.h>
#include <cuda_fp16.h>
#include <math.h>
#include <stdint.h>

#define NB 32
#define NT 512
#define NC 256
#define ND 1024
#define NH 16
#define NL 6
#define NFF 4096
#define NO 256
#define NQ 8
#define NK 1024
#define NTOK (NB*NT)

#define QKV_SZ  (ND*3*ND)
#define PROJ_SZ (ND*ND)
#define FF1_SZ  (ND*NFF)
#define FF2_SZ  (NFF*ND)
#define OFF_WIN 0
#define OFF_QKV (NC*ND)
#define OFF_PROJ (OFF_QKV + 6*QKV_SZ)
#define OFF_FF1  (OFF_PROJ + 6*PROJ_SZ)
#define OFF_FF2  (OFF_FF1 + 6*FF1_SZ)
#define W_TOTAL  (OFF_FF2 + 6*FF2_SZ)

__device__ float g_h  [(size_t)NTOK * ND];
__device__ float g_qkv[(size_t)NTOK * 3 * ND];
__device__ float g_last[NB * ND];
__device__ float g_z1  [NB * ND];
__device__ float g_z   [NB * NO];

__device__ __half g_wf [W_TOTAL];               // weights fp16 [N,K]
__device__ __half g_af [(size_t)NTOK * ND];     // activation fp16
__device__ __half g_ff [(size_t)NTOK * NFF];
__device__ __half g_xf [(size_t)NTOK * NC];

__device__ __forceinline__ float gelu_exact(float v) {
    return 0.5f * v * (1.0f + erff(v * 0.70710678118654752f));
}
__device__ __forceinline__ uint32_t smem_u32(const void* p) {
    uint32_t a;
    asm("{ .reg .u64 t; cvta.to.shared.u64 t, %1; cvt.u32.u64 %0, t; }"
        : "=r"(a) : "l"(p));
    return a;
}
__device__ __forceinline__ void cp16(uint32_t dst, const void* src) {
    asm volatile("cp.async.cg.shared.global [%0], [%1], 16;"
                 :: "r"(dst), "l"(src) : "memory");
}
#define CP_COMMIT() asm volatile("cp.async.commit_group;" ::: "memory")
#define CP_WAIT1()  asm volatile("cp.async.wait_group 1;" ::: "memory")
#define CP_WAIT0()  asm volatile("cp.async.wait_group 0;" ::: "memory")

__device__ __forceinline__ void ldsm_x4(uint32_t* r, uint32_t addr) {
    asm volatile("ldmatrix.sync.aligned.m8n8.x4.shared.b16 {%0,%1,%2,%3}, [%4];"
                 : "=r"(r[0]), "=r"(r[1]), "=r"(r[2]), "=r"(r[3]) : "r"(addr));
}
__device__ __forceinline__ void mma_f16(float* d, const uint32_t* a, const uint32_t* b) {
    asm volatile("mma.sync.aligned.m16n8k16.row.col.f32.f16.f16.f32 "
                 "{%0,%1,%2,%3}, {%4,%5,%6,%7}, {%8,%9}, {%0,%1,%2,%3};"
                 : "+f"(d[0]), "+f"(d[1]), "+f"(d[2]), "+f"(d[3])
                 : "r"(a[0]), "r"(a[1]), "r"(a[2]), "r"(a[3]),
                   "r"(b[0]), "r"(b[1]));
}

// ---------------------------------------------------------------------------
// fp16 single-pass GEMM. C[M,N] = A[M,K] @ W[K,N].
// A fp16 [M,K]; W pre-transposed fp16 [N,K]. fp32 accum.
// Block 128x128, BK=32, 256 thr (8 warps 2Mx4N, warp 64x32), 2-stage cp.async.
// Rows: 64B data + 16B pad = 80B stride (conflict-free ldmatrix).
// MODE 0: fp32+bias  1: +pos[(row%NT)*N+col]  2: gelu->fp16  3: +extra resid
// ---------------------------------------------------------------------------
#define MT_B   10240              // 128 rows * 80B
#define STG_B  (2*MT_B)           // A, B
#define GSMEM  (2*STG_B)          // 40960

__device__ __forceinline__ void load_stage(
    uint32_t sb, int c, int tid, int rowBase, int colBase, int K,
    const __half* __restrict__ A, const __half* __restrict__ B)
{
    size_t koff = (size_t)c * 32;
#pragma unroll
    for (int i = 0; i < 2; i++) {
        int lin = tid + (i << 8);
        int r = lin >> 2, q = lin & 3;
        uint32_t so = (uint32_t)(r * 80 + q * 16);
        cp16(sb + so,        A + (size_t)(rowBase + r) * K + koff + q * 8);
        cp16(sb + MT_B + so, B + (size_t)(colBase + r) * K + koff + q * 8);
    }
    CP_COMMIT();
}

template<int MODE>
__global__ __launch_bounds__(256)
void gemm_mma(const __half* __restrict__ A, const __half* __restrict__ B,
              const float* __restrict__ bias, const float* __restrict__ extra,
              float* __restrict__ Cf, __half* __restrict__ Ch,
              int M, int N, int K)
{
    extern __shared__ __align__(1024) unsigned char dynsmem[];
    uint32_t sbase = smem_u32(dynsmem);
    const int tid = threadIdx.x;
    const int lane = tid & 31;
    const int warp = tid >> 5;
    const int warpM = warp & 1;
    const int warpN = warp >> 1;
    const int rowBase = blockIdx.y * 128;
    const int colBase = blockIdx.x * 128;
    const int nc = K >> 5;

    float acc[4][4][4];
#pragma unroll
    for (int mt = 0; mt < 4; mt++)
#pragma unroll
        for (int nt = 0; nt < 4; nt++)
#pragma unroll
            for (int e = 0; e < 4; e++) acc[mt][nt][e] = 0.f;

    load_stage(sbase,         0, tid, rowBase, colBase, K, A, B);
    load_stage(sbase + STG_B, 1, tid, rowBase, colBase, K, A, B);

    const int aRow = warpM * 64 + (lane & 15);
    const uint32_t aColOff = (uint32_t)((lane >> 4) * 16);
    const int bRow = warpN * 32 + ((lane >> 4) & 1) * 8 + (lane & 7);
    const uint32_t bColOff = (uint32_t)(((lane >> 3) & 1) * 16);

    for (int c = 0; c < nc; c++) {
        if (c + 1 < nc) { CP_WAIT1(); } else { CP_WAIT0(); }
        __syncthreads();
        uint32_t sb = sbase + (uint32_t)(c & 1) * STG_B;

#pragma unroll
        for (int kk = 0; kk < 2; kk++) {
            uint32_t kb = (uint32_t)(kk * 32);
            uint32_t ah[4][4];
#pragma unroll
            for (int mt = 0; mt < 4; mt++)
                ldsm_x4(ah[mt], sb + (uint32_t)((aRow + mt * 16) * 80) + kb + aColOff);
            uint32_t r0[4], r1[4];
            ldsm_x4(r0, sb + MT_B + (uint32_t)(bRow * 80) + kb + bColOff);
            ldsm_x4(r1, sb + MT_B + (uint32_t)((bRow + 16) * 80) + kb + bColOff);
            uint32_t b0[2] = {r0[0], r0[1]}, b1[2] = {r0[2], r0[3]};
            uint32_t b2[2] = {r1[0], r1[1]}, b3[2] = {r1[2], r1[3]};
#pragma unroll
            for (int mt = 0; mt < 4; mt++) {
                mma_f16(acc[mt][0], ah[mt], b0);
                mma_f16(acc[mt][1], ah[mt], b1);
                mma_f16(acc[mt][2], ah[mt], b2);
                mma_f16(acc[mt][3], ah[mt], b3);
            }
        }
        __syncthreads();
        if (c + 2 < nc)
            load_stage(sbase + (uint32_t)(c & 1) * STG_B, c + 2, tid,
                       rowBase, colBase, K, A, B);
    }

#pragma unroll
    for (int mt = 0; mt < 4; mt++) {
        int row0 = rowBase + warpM * 64 + mt * 16 + (lane >> 2);
#pragma unroll
        for (int nt = 0; nt < 4; nt++) {
            int col = colBase + warpN * 32 + nt * 8 + (lane & 3) * 2;
            float b0 = bias[col], b1 = bias[col + 1];
#pragma unroll
            for (int half = 0; half < 2; half++) {
                int row = row0 + half * 8;
                float v0 = acc[mt][nt][half * 2 + 0] + b0;
                float v1 = acc[mt][nt][half * 2 + 1] + b1;
                if (MODE == 1) {
                    size_t pr = (size_t)(row & (NT - 1)) * N + col;
                    v0 += extra[pr]; v1 += extra[pr + 1];
                }
                if (MODE == 3) {
                    size_t pr = (size_t)row * N + col;
                    v0 += extra[pr]; v1 += extra[pr + 1];
                }
                size_t o = (size_t)row * N + col;
                if (MODE == 2) {
                    v0 = gelu_exact(v0); v1 = gelu_exact(v1);
                    *(__half2*)(Ch + o) = __half2(__float2half(v0), __float2half(v1));
                } else {
                    Cf[o] = v0; Cf[o + 1] = v1;
                }
            }
        }
    }
}

// ---------------- weight transpose + fp16 convert ----------------
__global__ __launch_bounds__(256)
void tcvt(const float* __restrict__ W, __half* __restrict__ o, int K, int N)
{
    __shared__ float t[32][33];
    const int tx = threadIdx.x, ty = threadIdx.y;
    const int n0 = blockIdx.x * 32, k0 = blockIdx.y * 32;
#pragma unroll
    for (int i = 0; i < 4; i++)
        t[ty + 8 * i][tx] = W[(size_t)(k0 + ty + 8 * i) * N + n0 + tx];
    __syncthreads();
#pragma unroll
    for (int i = 0; i < 4; i++)
        o[(size_t)(n0 + ty + 8 * i) * K + k0 + tx] = __float2half(t[tx][ty + 8 * i]);
}

__global__ __launch_bounds__(256)
void xcvt(const float* __restrict__ x, __half* __restrict__ xf, int n) {
    int i = blockIdx.x * 256 + threadIdx.x;
    if (i < n) xf[i] = __float2half(x[i]);
}

// ---------------- LayerNorm: OUT=0 fp32, OUT=1 fp16 ----------------
template<int OUT>
__global__ __launch_bounds__(256)
void ln_kernel(const float* __restrict__ x, const float* __restrict__ g,
               const float* __restrict__ b, float* __restrict__ yf,
               __half* __restrict__ yh, size_t rowStride)
{
    __shared__ float red[18];
    const int row = blockIdx.x, tid = threadIdx.x;
    const float* xr = x + (size_t)row * rowStride;
    float4 v = ((const float4*)xr)[tid];
    float s  = v.x + v.y + v.z + v.w;
    float sq = v.x*v.x + v.y*v.y + v.z*v.z + v.w*v.w;
#pragma unroll
    for (int o = 16; o > 0; o >>= 1) {
        s  += __shfl_xor_sync(0xffffffffu, s,  o);
        sq += __shfl_xor_sync(0xffffffffu, sq, o);
    }
    if ((tid & 31) == 0) { red[tid >> 5] = s; red[8 + (tid >> 5)] = sq; }
    __syncthreads();
    if (tid < 32) {
        float ws = (tid < 8) ? red[tid]     : 0.f;
        float wq = (tid < 8) ? red[8 + tid] : 0.f;
#pragma unroll
        for (int o = 4; o > 0; o >>= 1) {
            ws += __shfl_xor_sync(0xffffffffu, ws, o);
            wq += __shfl_xor_sync(0xffffffffu, wq, o);
        }
        if (tid == 0) { red[16] = ws; red[17] = wq; }
    }
    __syncthreads();
    float mean = red[16] * (1.f / ND);
    float var  = red[17] * (1.f / ND) - mean * mean;
    float rstd = rsqrtf(var + 1e-5f);
    float4 gg = ((const float4*)g)[tid];
    float4 bb = ((const float4*)b)[tid];
    float o0 = (v.x - mean) * rstd * gg.x + bb.x;
    float o1 = (v.y - mean) * rstd * gg.y + bb.y;
    float o2 = (v.z - mean) * rstd * gg.z + bb.z;
    float o3 = (v.w - mean) * rstd * gg.w + bb.w;
    if (OUT == 0) {
        float4 o4 = {o0, o1, o2, o3};
        ((float4*)(yf + (size_t)row * ND))[tid] = o4;
    } else {
        size_t base = (size_t)row * ND + tid * 4;
        *(__half2*)(yh + base)     = __half2(__float2half(o0), __float2half(o1));
        *(__half2*)(yh + base + 2) = __half2(__float2half(o2), __float2half(o3));
    }
}

// ---------------- flash attention (fp32 SIMT), fp16 out ----------------
#define AST 65
#define ATTN_SMEM (4 * 64 * AST * (int)sizeof(float))

__global__ __launch_bounds__(256)
void attn_kernel(const float* __restrict__ qkv, __half* __restrict__ oh)
{
    extern __shared__ __align__(1024) unsigned char dynsmem[];
    float* sm = (float*)dynsmem;
    float* sQ = sm;
    float* sK = sQ + 64 * AST;
    float* sV = sK + 64 * AST;
    float* sP = sV + 64 * AST;

    const int qt = blockIdx.x, h = blockIdx.y, b = blockIdx.z;
    const int tid = threadIdx.x;
    const int r = tid >> 2;
    const int cg = tid & 3;
    const float scale = 0.125f;

    for (int l = tid; l < 64 * 64; l += 256) {
        int m = l >> 6, d = l & 63;
        sQ[m * AST + d] =
            qkv[(size_t)(b * NT + qt * 64 + m) * (3 * ND) + h * 64 + d];
    }

    float m_run = -1e30f, l_run = 0.f;
    float accO[16];
#pragma unroll
    for (int j = 0; j < 16; j++) accO[j] = 0.f;
    const int qi = qt * 64 + r;

    for (int kt = 0; kt <= qt; kt++) {
        __syncthreads();
        for (int l = tid; l < 64 * 64; l += 256) {
            int m = l >> 6, d = l & 63;
            size_t base = (size_t)(b * NT + kt * 64 + m) * (3 * ND) + h * 64 + d;
            sK[m * AST + d] = qkv[base + ND];
            sV[m * AST + d] = qkv[base + 2 * ND];
        }
        __syncthreads();

        float s[16];
#pragma unroll
        for (int j = 0; j < 16; j++) s[j] = 0.f;
        for (int d = 0; d < 64; d++) {
            float qv = sQ[r * AST + d];
#pragma unroll
            for (int j = 0; j < 16; j++)
                s[j] += qv * sK[(cg + 4 * j) * AST + d];
        }
        float tmax = -1e30f;
#pragma unroll
        for (int j = 0; j < 16; j++) {
            int ki = kt * 64 + cg + 4 * j;
            s[j] = (ki <= qi) ? s[j] * scale : -1e30f;
            tmax = fmaxf(tmax, s[j]);
        }
        tmax = fmaxf(tmax, __shfl_xor_sync(0xffffffffu, tmax, 1));
        tmax = fmaxf(tmax, __shfl_xor_sync(0xffffffffu, tmax, 2));
        float m_new = fmaxf(m_run, tmax);
        float corr = expf(m_run - m_new);
        float lsum = 0.f;
#pragma unroll
        for (int j = 0; j < 16; j++) {
            float p = expf(s[j] - m_new);
            lsum += p;
            sP[r * AST + cg + 4 * j] = p;
        }
        lsum += __shfl_xor_sync(0xffffffffu, lsum, 1);
        lsum += __shfl_xor_sync(0xffffffffu, lsum, 2);
        l_run = l_run * corr + lsum;
        m_run = m_new;
#pragma unroll
        for (int j = 0; j < 16; j++) accO[j] *= corr;
        __syncthreads();

        for (int c = 0; c < 64; c++) {
            float p = sP[r * AST + c];
#pragma unroll
            for (int j = 0; j < 16; j++)
                accO[j] += p * sV[c * AST + cg + 4 * j];
        }
    }

    float inv = 1.f / l_run;
    size_t token = (size_t)(b * NT + qt * 64 + r);
#pragma unroll
    for (int j = 0; j < 16; j++)
        oh[token * ND + h * 64 + cg + 4 * j] = __float2half(accO[j] * inv);
}

// ---------------- head + RVQ ----------------
__global__ __launch_bounds__(256)
void small_gemm(const float* __restrict__ A, const float* __restrict__ W,
                const float* __restrict__ bias, float* __restrict__ out,
                int K, int N, int doGelu)
{
    __shared__ float sA[ND];
    const int row = blockIdx.x, tid = threadIdx.x;
    for (int i = tid; i < K; i += 256) sA[i] = A[(size_t)row * K + i];
    __syncthreads();
    for (int col = tid; col < N; col += 256) {
        float acc = 0.f;
        for (int k = 0; k < K; k++) acc += sA[k] * W[(size_t)k * N + col];
        acc += bias[col];
        if (doGelu) acc = gelu_exact(acc);
        out[(size_t)row * N + col] = acc;
    }
}

__global__ __launch_bounds__(256)
void rvq_kernel(const float* __restrict__ z, const float* __restrict__ codebooks,
                const float* __restrict__ layer_scales, float* __restrict__ out)
{
    __shared__ float res[NO];
    __shared__ float bestd[256];
    __shared__ int   besti[256];
    const int row = blockIdx.x, tid = threadIdx.x;
    res[tid] = z[(size_t)row * NO + tid];
    float outv = 0.f;
    for (int q = 0; q < NQ; q++) {
        __syncthreads();
        const float* cb = codebooks + (size_t)q * NK * NO;
        float bd = 1e30f; int bi = 0;
        for (int c = tid; c < NK; c += 256) {
            const float* e = cb + (size_t)c * NO;
            float dot = 0.f, nrm = 0.f;
            for (int d = 0; d < NO; d += 4) {
                float4 e4 = *(const float4*)(e + d);
                dot += res[d]*e4.x + res[d+1]*e4.y + res[d+2]*e4.z + res[d+3]*e4.w;
                nrm += e4.x*e4.x + e4.y*e4.y + e4.z*e4.z + e4.w*e4.w;
            }
            float dist = nrm - 2.f * dot;
            if (dist < bd) { bd = dist; bi = c; }
        }
        bestd[tid] = bd; besti[tid] = bi;
        __syncthreads();
        for (int sft = 128; sft > 0; sft >>= 1) {
            if (tid < sft) {
                float od = bestd[tid + sft]; int oi = besti[tid + sft];
                if (od < bestd[tid] || (od == bestd[tid] && oi < besti[tid])) {
                    bestd[tid] = od; besti[tid] = oi;
                }
            }
            __syncthreads();
        }
        int best = besti[0];
        float sig = 1.f / (1.f + expf(-layer_scales[q]));
        float ev = cb[(size_t)best * NO + tid];
        outv += sig * ev;
        res[tid] = res[tid] - ev;
    }
    out[(size_t)row * NO + tid] = outv;
}

// ---------------------------------------------------------------------------
extern "C" void kernel_launch(void* const* d_in, const int* in_sizes, int n_in,
                              void* d_out, int out_size)
{
    const float* x      = (const float*)d_in[0];
    const float* w_in   = (const float*)d_in[1];
    const float* b_in   = (const float*)d_in[2];
    const float* pos    = (const float*)d_in[3];
    const float* ln1_g  = (const float*)d_in[4];
    const float* ln1_b  = (const float*)d_in[5];
    const float* qkv_w  = (const float*)d_in[6];
    const float* qkv_b  = (const float*)d_in[7];
    const float* proj_w = (const float*)d_in[8];
    const float* proj_b = (const float*)d_in[9];
    const float* ln2_g  = (const float*)d_in[10];
    const float* ln2_b  = (const float*)d_in[11];
    const float* ff1_w  = (const float*)d_in[12];
    const float* ff1_b  = (const float*)d_in[13];
    const float* ff2_w  = (const float*)d_in[14];
    const float* ff2_b  = (const float*)d_in[15];
    const float* lnf_g  = (const float*)d_in[16];
    const float* lnf_b  = (const float*)d_in[17];
    const float* out1_w = (const float*)d_in[18];
    const float* out1_b = (const float*)d_in[19];
    const float* out2_w = (const float*)d_in[20];
    const float* out2_b = (const float*)d_in[21];
    const float* codebooks    = (const float*)d_in[22];
    const float* layer_scales = (const float*)d_in[23];

    float *h, *qkv, *last, *z1, *z;
    __half *wf, *af, *ff, *xf;
    cudaGetSymbolAddress((void**)&h,    g_h);
    cudaGetSymbolAddress((void**)&qkv,  g_qkv);
    cudaGetSymbolAddress((void**)&last, g_last);
    cudaGetSymbolAddress((void**)&z1,   g_z1);
    cudaGetSymbolAddress((void**)&z,    g_z);
    cudaGetSymbolAddress((void**)&wf,   g_wf);
    cudaGetSymbolAddress((void**)&af,   g_af);
    cudaGetSymbolAddress((void**)&ff,   g_ff);
    cudaGetSymbolAddress((void**)&xf,   g_xf);

    cudaFuncSetAttribute(attn_kernel, cudaFuncAttributeMaxDynamicSharedMemorySize, ATTN_SMEM);
    cudaFuncSetAttribute(gemm_mma<0>, cudaFuncAttributeMaxDynamicSharedMemorySize, GSMEM);
    cudaFuncSetAttribute(gemm_mma<1>, cudaFuncAttributeMaxDynamicSharedMemorySize, GSMEM);
    cudaFuncSetAttribute(gemm_mma<2>, cudaFuncAttributeMaxDynamicSharedMemorySize, GSMEM);
    cudaFuncSetAttribute(gemm_mma<3>, cudaFuncAttributeMaxDynamicSharedMemorySize, GSMEM);

    const dim3 thr(256);
    const dim3 tthr(32, 8);

    // ---- conversions ----
    xcvt<<<(NTOK * NC + 255) / 256, thr>>>(x, xf, NTOK * NC);
    tcvt<<<dim3(ND/32, NC/32), tthr>>>(w_in, wf + OFF_WIN, NC, ND);
    for (int l = 0; l < NL; l++) {
        tcvt<<<dim3(3*ND/32, ND/32), tthr>>>(qkv_w + (size_t)l*QKV_SZ,
            wf + OFF_QKV + (size_t)l*QKV_SZ, ND, 3*ND);
        tcvt<<<dim3(ND/32, ND/32), tthr>>>(proj_w + (size_t)l*PROJ_SZ,
            wf + OFF_PROJ + (size_t)l*PROJ_SZ, ND, ND);
        tcvt<<<dim3(NFF/32, ND/32), tthr>>>(ff1_w + (size_t)l*FF1_SZ,
            wf + OFF_FF1 + (size_t)l*FF1_SZ, ND, NFF);
        tcvt<<<dim3(ND/32, NFF/32), tthr>>>(ff2_w + (size_t)l*FF2_SZ,
            wf + OFF_FF2 + (size_t)l*FF2_SZ, NFF, ND);
    }

    // ---- h = x @ w_in + b_in + pos ----
    gemm_mma<1><<<dim3(ND/128, NTOK/128), thr, GSMEM>>>(
        xf, wf + OFF_WIN, b_in, pos, h, nullptr, NTOK, ND, NC);

    for (int l = 0; l < NL; l++) {
        ln_kernel<1><<<NTOK, thr>>>(h, ln1_g + (size_t)l*ND, ln1_b + (size_t)l*ND,
                                    nullptr, af, ND);
        gemm_mma<0><<<dim3(3*ND/128, NTOK/128), thr, GSMEM>>>(
            af, wf + OFF_QKV + (size_t)l*QKV_SZ,
            qkv_b + (size_t)l*3*ND, nullptr, qkv, nullptr, NTOK, 3*ND, ND);
        attn_kernel<<<dim3(NT/64, NH, NB), thr, ATTN_SMEM>>>(qkv, af);
        gemm_mma<3><<<dim3(ND/128, NTOK/128), thr, GSMEM>>>(
            af, wf + OFF_PROJ + (size_t)l*PROJ_SZ,
            proj_b + (size_t)l*ND, h, h, nullptr, NTOK, ND, ND);
        ln_kernel<1><<<NTOK, thr>>>(h, ln2_g + (size_t)l*ND, ln2_b + (size_t)l*ND,
                                    nullptr, af, ND);
        gemm_mma<2><<<dim3(NFF/128, NTOK/128), thr, GSMEM>>>(
            af, wf + OFF_FF1 + (size_t)l*FF1_SZ,
            ff1_b + (size_t)l*NFF, nullptr, nullptr, ff, NTOK, NFF, ND);
        gemm_mma<3><<<dim3(ND/128, NTOK/128), thr, GSMEM>>>(
            ff, wf + OFF_FF2 + (size_t)l*FF2_SZ,
            ff2_b + (size_t)l*ND, h, h, nullptr, NTOK, ND, NFF);
    }

    // ---- head ----
    ln_kernel<0><<<NB, thr>>>(h + (size_t)(NT - 1) * ND, lnf_g, lnf_b,
                              last, nullptr, (size_t)NT * ND);
    small_gemm<<<NB, thr>>>(last, out1_w, out1_b, z1, ND, ND, 1);
    small_gemm<<<NB, thr>>>(z1, out2_w, out2_b, z, ND, NO, 0);
    rvq_kernel<<<NB, thr>>>(z, codebooks, layer_scales, (float*)d_out);
}

// round 10
// speedup vs baseline: 7.6195x; 1.6556x over previous
#include <cuda_runtime.h>
#include <cuda_fp16.h>
#include <math.h>
#include <stdint.h>

#define NB 32
#define NT 512
#define NC 256
#define ND 1024
#define NH 16
#define NL 6
#define NFF 4096
#define NO 256
#define NQ 8
#define NK 1024
#define NTOK (NB*NT)

#define QKV_SZ  (ND*3*ND)
#define PROJ_SZ (ND*ND)
#define FF1_SZ  (ND*NFF)
#define FF2_SZ  (NFF*ND)
#define OFF_WIN 0
#define OFF_QKV (NC*ND)
#define OFF_PROJ (OFF_QKV + 6*QKV_SZ)
#define OFF_FF1  (OFF_PROJ + 6*PROJ_SZ)
#define OFF_FF2  (OFF_FF1 + 6*FF1_SZ)
#define W_TOTAL  (OFF_FF2 + 6*FF2_SZ)

__device__ float g_h  [(size_t)NTOK * ND];
__device__ float g_last[NB * ND];
__device__ float g_z1  [NB * ND];
__device__ float g_z   [NB * NO];

__device__ __align__(16) __half g_wf  [W_TOTAL];
__device__ __align__(16) __half g_af  [(size_t)NTOK * ND];
__device__ __align__(16) __half g_ff  [(size_t)NTOK * NFF];
__device__ __align__(16) __half g_xf  [(size_t)NTOK * NC];
__device__ __align__(16) __half g_qkvh[(size_t)NTOK * 3 * ND];

__device__ __forceinline__ float gelu_exact(float v) {
    return 0.5f * v * (1.0f + erff(v * 0.70710678118654752f));
}
__device__ __forceinline__ uint32_t smem_u32(const void* p) {
    uint32_t a;
    asm("{ .reg .u64 t; cvta.to.shared.u64 t, %1; cvt.u32.u64 %0, t; }"
        : "=r"(a) : "l"(p));
    return a;
}
__device__ __forceinline__ void cp16(uint32_t dst, const void* src) {
    asm volatile("cp.async.cg.shared.global [%0], [%1], 16;"
                 :: "r"(dst), "l"(src) : "memory");
}
#define CP_COMMIT() asm volatile("cp.async.commit_group;" ::: "memory")
#define CP_WAIT1()  asm volatile("cp.async.wait_group 1;" ::: "memory")
#define CP_WAIT0()  asm volatile("cp.async.wait_group 0;" ::: "memory")

__device__ __forceinline__ void ldsm_x4(uint32_t* r, uint32_t addr) {
    asm volatile("ldmatrix.sync.aligned.m8n8.x4.shared.b16 {%0,%1,%2,%3}, [%4];"
                 : "=r"(r[0]), "=r"(r[1]), "=r"(r[2]), "=r"(r[3]) : "r"(addr));
}
__device__ __forceinline__ void ldsm_x4_t(uint32_t* r, uint32_t addr) {
    asm volatile("ldmatrix.sync.aligned.m8n8.x4.trans.shared.b16 {%0,%1,%2,%3}, [%4];"
                 : "=r"(r[0]), "=r"(r[1]), "=r"(r[2]), "=r"(r[3]) : "r"(addr));
}
__device__ __forceinline__ void mma_f16(float* d, const uint32_t* a, const uint32_t* b) {
    asm volatile("mma.sync.aligned.m16n8k16.row.col.f32.f16.f16.f32 "
                 "{%0,%1,%2,%3}, {%4,%5,%6,%7}, {%8,%9}, {%0,%1,%2,%3};"
                 : "+f"(d[0]), "+f"(d[1]), "+f"(d[2]), "+f"(d[3])
                 : "r"(a[0]), "r"(a[1]), "r"(a[2]), "r"(a[3]),
                   "r"(b[0]), "r"(b[1]));
}

// ---------------------------------------------------------------------------
// fp16 GEMM. C[M,N] = A[M,K] @ W[K,N]. A fp16 [M,K]; W pre-transposed [N,K].
// Block 128x128, BK=32, 256 thr (8 warps 2Mx4N, warp 64x32), 2-stage cp.async.
// MODE 0: fp32+bias  1: +pos  2: gelu->fp16  3: +extra resid  4: fp16+bias
// ---------------------------------------------------------------------------
#define MT_B   10240
#define STG_B  (2*MT_B)
#define GSMEM  (2*STG_B)

__device__ __forceinline__ void load_stage(
    uint32_t sb, int c, int tid, int rowBase, int colBase, int K,
    const __half* __restrict__ A, const __half* __restrict__ B)
{
    size_t koff = (size_t)c * 32;
#pragma unroll
    for (int i = 0; i < 2; i++) {
        int lin = tid + (i << 8);
        int r = lin >> 2, q = lin & 3;
        uint32_t so = (uint32_t)(r * 80 + q * 16);
        cp16(sb + so,        A + (size_t)(rowBase + r) * K + koff + q * 8);
        cp16(sb + MT_B + so, B + (size_t)(colBase + r) * K + koff + q * 8);
    }
    CP_COMMIT();
}

template<int MODE>
__global__ __launch_bounds__(256)
void gemm_mma(const __half* __restrict__ A, const __half* __restrict__ B,
              const float* __restrict__ bias, const float* __restrict__ extra,
              float* __restrict__ Cf, __half* __restrict__ Ch,
              int M, int N, int K)
{
    extern __shared__ __align__(1024) unsigned char dynsmem[];
    uint32_t sbase = smem_u32(dynsmem);
    const int tid = threadIdx.x;
    const int lane = tid & 31;
    const int warp = tid >> 5;
    const int warpM = warp & 1;
    const int warpN = warp >> 1;
    const int rowBase = blockIdx.y * 128;
    const int colBase = blockIdx.x * 128;
    const int nc = K >> 5;

    float acc[4][4][4];
#pragma unroll
    for (int mt = 0; mt < 4; mt++)
#pragma unroll
        for (int nt = 0; nt < 4; nt++)
#pragma unroll
            for (int e = 0; e < 4; e++) acc[mt][nt][e] = 0.f;

    load_stage(sbase,         0, tid, rowBase, colBase, K, A, B);
    load_stage(sbase + STG_B, 1, tid, rowBase, colBase, K, A, B);

    const int aRow = warpM * 64 + (lane & 15);
    const uint32_t aColOff = (uint32_t)((lane >> 4) * 16);
    const int bRow = warpN * 32 + ((lane >> 4) & 1) * 8 + (lane & 7);
    const uint32_t bColOff = (uint32_t)(((lane >> 3) & 1) * 16);

    for (int c = 0; c < nc; c++) {
        if (c + 1 < nc) { CP_WAIT1(); } else { CP_WAIT0(); }
        __syncthreads();
        uint32_t sb = sbase + (uint32_t)(c & 1) * STG_B;

#pragma unroll
        for (int kk = 0; kk < 2; kk++) {
            uint32_t kb = (uint32_t)(kk * 32);
            uint32_t ah[4][4];
#pragma unroll
            for (int mt = 0; mt < 4; mt++)
                ldsm_x4(ah[mt], sb + (uint32_t)((aRow + mt * 16) * 80) + kb + aColOff);
            uint32_t r0[4], r1[4];
            ldsm_x4(r0, sb + MT_B + (uint32_t)(bRow * 80) + kb + bColOff);
            ldsm_x4(r1, sb + MT_B + (uint32_t)((bRow + 16) * 80) + kb + bColOff);
#pragma unroll
            for (int mt = 0; mt < 4; mt++) {
                mma_f16(acc[mt][0], ah[mt], r0);
                mma_f16(acc[mt][1], ah[mt], r0 + 2);
                mma_f16(acc[mt][2], ah[mt], r1);
                mma_f16(acc[mt][3], ah[mt], r1 + 2);
            }
        }
        __syncthreads();
        if (c + 2 < nc)
            load_stage(sbase + (uint32_t)(c & 1) * STG_B, c + 2, tid,
                       rowBase, colBase, K, A, B);
    }

#pragma unroll
    for (int mt = 0; mt < 4; mt++) {
        int row0 = rowBase + warpM * 64 + mt * 16 + (lane >> 2);
#pragma unroll
        for (int nt = 0; nt < 4; nt++) {
            int col = colBase + warpN * 32 + nt * 8 + (lane & 3) * 2;
            float b0 = bias[col], b1 = bias[col + 1];
#pragma unroll
            for (int half = 0; half < 2; half++) {
                int row = row0 + half * 8;
                float v0 = acc[mt][nt][half * 2 + 0] + b0;
                float v1 = acc[mt][nt][half * 2 + 1] + b1;
                if (MODE == 1) {
                    size_t pr = (size_t)(row & (NT - 1)) * N + col;
                    v0 += extra[pr]; v1 += extra[pr + 1];
                }
                if (MODE == 3) {
                    size_t pr = (size_t)row * N + col;
                    v0 += extra[pr]; v1 += extra[pr + 1];
                }
                size_t o = (size_t)row * N + col;
                if (MODE == 2 || MODE == 4) {
                    if (MODE == 2) { v0 = gelu_exact(v0); v1 = gelu_exact(v1); }
                    *(__half2*)(Ch + o) = __half2(__float2half(v0), __float2half(v1));
                } else {
                    Cf[o] = v0; Cf[o + 1] = v1;
                }
            }
        }
    }
}

// ---------------- weight transpose + fp16 convert ----------------
__global__ __launch_bounds__(256)
void tcvt(const float* __restrict__ W, __half* __restrict__ o, int K, int N)
{
    __shared__ float t[32][33];
    const int tx = threadIdx.x, ty = threadIdx.y;
    const int n0 = blockIdx.x * 32, k0 = blockIdx.y * 32;
#pragma unroll
    for (int i = 0; i < 4; i++)
        t[ty + 8 * i][tx] = W[(size_t)(k0 + ty + 8 * i) * N + n0 + tx];
    __syncthreads();
#pragma unroll
    for (int i = 0; i < 4; i++)
        o[(size_t)(n0 + ty + 8 * i) * K + k0 + tx] = __float2half(t[tx][ty + 8 * i]);
}

__global__ __launch_bounds__(256)
void xcvt(const float* __restrict__ x, __half* __restrict__ xf, int n) {
    int i = blockIdx.x * 256 + threadIdx.x;
    if (i < n) xf[i] = __float2half(x[i]);
}

// ---------------- LayerNorm: OUT=0 fp32, OUT=1 fp16 ----------------
template<int OUT>
__global__ __launch_bounds__(256)
void ln_kernel(const float* __restrict__ x, const float* __restrict__ g,
               const float* __restrict__ b, float* __restrict__ yf,
               __half* __restrict__ yh, size_t rowStride)
{
    __shared__ float red[18];
    const int row = blockIdx.x, tid = threadIdx.x;
    const float* xr = x + (size_t)row * rowStride;
    float4 v = ((const float4*)xr)[tid];
    float s  = v.x + v.y + v.z + v.w;
    float sq = v.x*v.x + v.y*v.y + v.z*v.z + v.w*v.w;
#pragma unroll
    for (int o = 16; o > 0; o >>= 1) {
        s  += __shfl_xor_sync(0xffffffffu, s,  o);
        sq += __shfl_xor_sync(0xffffffffu, sq, o);
    }
    if ((tid & 31) == 0) { red[tid >> 5] = s; red[8 + (tid >> 5)] = sq; }
    __syncthreads();
    if (tid < 32) {
        float ws = (tid < 8) ? red[tid]     : 0.f;
        float wq = (tid < 8) ? red[8 + tid] : 0.f;
#pragma unroll
        for (int o = 4; o > 0; o >>= 1) {
            ws += __shfl_xor_sync(0xffffffffu, ws, o);
            wq += __shfl_xor_sync(0xffffffffu, wq, o);
        }
        if (tid == 0) { red[16] = ws; red[17] = wq; }
    }
    __syncthreads();
    float mean = red[16] * (1.f / ND);
    float var  = red[17] * (1.f / ND) - mean * mean;
    float rstd = rsqrtf(var + 1e-5f);
    float4 gg = ((const float4*)g)[tid];
    float4 bb = ((const float4*)b)[tid];
    float o0 = (v.x - mean) * rstd * gg.x + bb.x;
    float o1 = (v.y - mean) * rstd * gg.y + bb.y;
    float o2 = (v.z - mean) * rstd * gg.z + bb.z;
    float o3 = (v.w - mean) * rstd * gg.w + bb.w;
    if (OUT == 0) {
        float4 o4 = {o0, o1, o2, o3};
        ((float4*)(yf + (size_t)row * ND))[tid] = o4;
    } else {
        size_t base = (size_t)row * ND + tid * 4;
        *(__half2*)(yh + base)     = __half2(__float2half(o0), __float2half(o1));
        *(__half2*)(yh + base + 2) = __half2(__float2half(o2), __float2half(o3));
    }
}

// ---------------------------------------------------------------------------
// Tensor-core flash attention, causal, HD=64. qkv fp16 [tok][3ND]; out fp16.
// 128 thr (4 warps); warp w owns q-rows [16w,16w+16). Per ktile:
// S = Q K^T (non-trans ldsm both), in-register softmax, P->A-frags, O += P V
// (ldmatrix.trans on V). smem tiles 64 rows x 128B data + 16B pad = 144B.
// ---------------------------------------------------------------------------
#define ASTB 144

__global__ __launch_bounds__(128)
void attn_mma(const __half* __restrict__ qkv, __half* __restrict__ oh)
{
    __shared__ __align__(16) unsigned char sQ[64 * ASTB];
    __shared__ __align__(16) unsigned char sK[64 * ASTB];
    __shared__ __align__(16) unsigned char sV[64 * ASTB];
    const int qt = blockIdx.x, h = blockIdx.y, b = blockIdx.z;
    const int tid = threadIdx.x;
    const int lane = tid & 31, w = tid >> 5;
    uint32_t q_s = smem_u32(sQ), k_s = smem_u32(sK), v_s = smem_u32(sV);

    // load Q tile (fp16, 16B per access)
    {
        size_t tok0 = (size_t)(b * NT + qt * 64);
#pragma unroll
        for (int i = 0; i < 4; i++) {
            int idx = tid + i * 128;
            int m = idx >> 3, dq = (idx & 7) * 8;
            *(uint4*)(sQ + m * ASTB + dq * 2) =
                *(const uint4*)(qkv + (tok0 + m) * (3 * ND) + h * 64 + dq);
        }
    }
    __syncthreads();

    uint32_t aQ[4][4];
    {
        uint32_t base = q_s + (uint32_t)((w * 16 + (lane & 15)) * ASTB)
                      + (uint32_t)((lane >> 4) * 16);
#pragma unroll
        for (int kc = 0; kc < 4; kc++) ldsm_x4(aQ[kc], base + kc * 32);
    }

    float oAcc[8][4];
#pragma unroll
    for (int nt = 0; nt < 8; nt++)
#pragma unroll
        for (int e = 0; e < 4; e++) oAcc[nt][e] = 0.f;
    float mA = -1e30f, mB = -1e30f, lA = 0.f, lB = 0.f;
    const int rowA = qt * 64 + w * 16 + (lane >> 2);
    const int rowB = rowA + 8;
    const float scale = 0.125f;

    for (int kt = 0; kt <= qt; kt++) {
        __syncthreads();
        {
            size_t tok0 = (size_t)(b * NT + kt * 64);
#pragma unroll
            for (int i = 0; i < 4; i++) {
                int idx = tid + i * 128;
                int m = idx >> 3, dq = (idx & 7) * 8;
                const __half* src = qkv + (tok0 + m) * (3 * ND) + ND + h * 64 + dq;
                *(uint4*)(sK + m * ASTB + dq * 2) = *(const uint4*)src;
                *(uint4*)(sV + m * ASTB + dq * 2) = *(const uint4*)(src + ND);
            }
        }
        __syncthreads();

        // S = Q K^T
        float sAcc[8][4];
#pragma unroll
        for (int nt = 0; nt < 8; nt++)
#pragma unroll
            for (int e = 0; e < 4; e++) sAcc[nt][e] = 0.f;
#pragma unroll
        for (int ng = 0; ng < 4; ng++) {
            uint32_t rbase = k_s
                + (uint32_t)((ng * 16 + ((lane >> 4) & 1) * 8 + (lane & 7)) * ASTB)
                + (uint32_t)(((lane >> 3) & 1) * 16);
#pragma unroll
            for (int kc = 0; kc < 4; kc++) {
                uint32_t r[4];
                ldsm_x4(r, rbase + kc * 32);
                mma_f16(sAcc[2 * ng],     aQ[kc], r);
                mma_f16(sAcc[2 * ng + 1], aQ[kc], r + 2);
            }
        }

        // mask + scale + online softmax (rows A: e0,e1; rows B: e2,e3)
        int colBase = kt * 64 + (lane & 3) * 2;
        float tA = -1e30f, tB = -1e30f;
#pragma unroll
        for (int nt = 0; nt < 8; nt++) {
            int c0 = colBase + nt * 8, c1 = c0 + 1;
            sAcc[nt][0] = (c0 <= rowA) ? sAcc[nt][0] * scale : -1e30f;
            sAcc[nt][1] = (c1 <= rowA) ? sAcc[nt][1] * scale : -1e30f;
            sAcc[nt][2] = (c0 <= rowB) ? sAcc[nt][2] * scale : -1e30f;
            sAcc[nt][3] = (c1 <= rowB) ? sAcc[nt][3] * scale : -1e30f;
            tA = fmaxf(tA, fmaxf(sAcc[nt][0], sAcc[nt][1]));
            tB = fmaxf(tB, fmaxf(sAcc[nt][2], sAcc[nt][3]));
        }
        tA = fmaxf(tA, __shfl_xor_sync(0xffffffffu, tA, 1));
        tA = fmaxf(tA, __shfl_xor_sync(0xffffffffu, tA, 2));
        tB = fmaxf(tB, __shfl_xor_sync(0xffffffffu, tB, 1));
        tB = fmaxf(tB, __shfl_xor_sync(0xffffffffu, tB, 2));
        float mnA = fmaxf(mA, tA), mnB = fmaxf(mB, tB);
        float corrA = expf(mA - mnA), corrB = expf(mB - mnB);
        float lsA = 0.f, lsB = 0.f;
#pragma unroll
        for (int nt = 0; nt < 8; nt++) {
            sAcc[nt][0] = expf(sAcc[nt][0] - mnA);
            sAcc[nt][1] = expf(sAcc[nt][1] - mnA);
            sAcc[nt][2] = expf(sAcc[nt][2] - mnB);
            sAcc[nt][3] = expf(sAcc[nt][3] - mnB);
            lsA += sAcc[nt][0] + sAcc[nt][1];
            lsB += sAcc[nt][2] + sAcc[nt][3];
        }
        lsA += __shfl_xor_sync(0xffffffffu, lsA, 1);
        lsA += __shfl_xor_sync(0xffffffffu, lsA, 2);
        lsB += __shfl_xor_sync(0xffffffffu, lsB, 1);
        lsB += __shfl_xor_sync(0xffffffffu, lsB, 2);
        lA = lA * corrA + lsA; mA = mnA;
        lB = lB * corrB + lsB; mB = mnB;
#pragma unroll
        for (int nt = 0; nt < 8; nt++) {
            oAcc[nt][0] *= corrA; oAcc[nt][1] *= corrA;
            oAcc[nt][2] *= corrB; oAcc[nt][3] *= corrB;
        }

        // repack P accumulator frags -> A-operand frags (fp16)
        uint32_t aP[4][4];
#pragma unroll
        for (int kc = 0; kc < 4; kc++) {
            __half2 h0 = __floats2half2_rn(sAcc[2*kc][0],   sAcc[2*kc][1]);
            __half2 h1 = __floats2half2_rn(sAcc[2*kc][2],   sAcc[2*kc][3]);
            __half2 h2 = __floats2half2_rn(sAcc[2*kc+1][0], sAcc[2*kc+1][1]);
            __half2 h3 = __floats2half2_rn(sAcc[2*kc+1][2], sAcc[2*kc+1][3]);
            aP[kc][0] = *(uint32_t*)&h0; aP[kc][1] = *(uint32_t*)&h1;
            aP[kc][2] = *(uint32_t*)&h2; aP[kc][3] = *(uint32_t*)&h3;
        }

        // O += P V  (V via ldmatrix.trans: B[n=d][k=c])
#pragma unroll
        for (int dg = 0; dg < 4; dg++) {
#pragma unroll
            for (int kc = 0; kc < 4; kc++) {
                uint32_t r[4];
                uint32_t addr = v_s
                    + (uint32_t)((kc * 16 + ((lane >> 3) & 1) * 8 + (lane & 7)) * ASTB)
                    + (uint32_t)(dg * 32) + (uint32_t)(((lane >> 4) & 1) * 16);
                ldsm_x4_t(r, addr);
                mma_f16(oAcc[2 * dg],     aP[kc], r);
                mma_f16(oAcc[2 * dg + 1], aP[kc], r + 2);
            }
        }
    }

    float invA = 1.f / lA, invB = 1.f / lB;
    size_t tokA = (size_t)(b * NT) + rowA;
    size_t tokB = (size_t)(b * NT) + rowB;
    int col0 = h * 64 + (lane & 3) * 2;
#pragma unroll
    for (int nt = 0; nt < 8; nt++) {
        *(__half2*)(oh + tokA * ND + col0 + nt * 8) =
            __half2(__float2half(oAcc[nt][0] * invA), __float2half(oAcc[nt][1] * invA));
        *(__half2*)(oh + tokB * ND + col0 + nt * 8) =
            __half2(__float2half(oAcc[nt][2] * invB), __float2half(oAcc[nt][3] * invB));
    }
}

// ---------------- head + RVQ ----------------
__global__ __launch_bounds__(256)
void small_gemm(const float* __restrict__ A, const float* __restrict__ W,
                const float* __restrict__ bias, float* __restrict__ out,
                int K, int N, int doGelu)
{
    __shared__ float sA[ND];
    const int row = blockIdx.x, tid = threadIdx.x;
    for (int i = tid; i < K; i += 256) sA[i] = A[(size_t)row * K + i];
    __syncthreads();
    for (int col = tid; col < N; col += 256) {
        float acc = 0.f;
        for (int k = 0; k < K; k++) acc += sA[k] * W[(size_t)k * N + col];
        acc += bias[col];
        if (doGelu) acc = gelu_exact(acc);
        out[(size_t)row * N + col] = acc;
    }
}

__global__ __launch_bounds__(256)
void rvq_kernel(const float* __restrict__ z, const float* __restrict__ codebooks,
                const float* __restrict__ layer_scales, float* __restrict__ out)
{
    __shared__ float res[NO];
    __shared__ float bestd[256];
    __shared__ int   besti[256];
    const int row = blockIdx.x, tid = threadIdx.x;
    res[tid] = z[(size_t)row * NO + tid];
    float outv = 0.f;
    for (int q = 0; q < NQ; q++) {
        __syncthreads();
        const float* cb = codebooks + (size_t)q * NK * NO;
        float bd = 1e30f; int bi = 0;
        for (int c = tid; c < NK; c += 256) {
            const float* e = cb + (size_t)c * NO;
            float dot = 0.f, nrm = 0.f;
            for (int d = 0; d < NO; d += 4) {
                float4 e4 = *(const float4*)(e + d);
                dot += res[d]*e4.x + res[d+1]*e4.y + res[d+2]*e4.z + res[d+3]*e4.w;
                nrm += e4.x*e4.x + e4.y*e4.y + e4.z*e4.z + e4.w*e4.w;
            }
            float dist = nrm - 2.f * dot;
            if (dist < bd) { bd = dist; bi = c; }
        }
        bestd[tid] = bd; besti[tid] = bi;
        __syncthreads();
        for (int sft = 128; sft > 0; sft >>= 1) {
            if (tid < sft) {
                float od = bestd[tid + sft]; int oi = besti[tid + sft];
                if (od < bestd[tid] || (od == bestd[tid] && oi < besti[tid])) {
                    bestd[tid] = od; besti[tid] = oi;
                }
            }
            __syncthreads();
        }
        int best = besti[0];
        float sig = 1.f / (1.f + expf(-layer_scales[q]));
        float ev = cb[(size_t)best * NO + tid];
        outv += sig * ev;
        res[tid] = res[tid] - ev;
    }
    out[(size_t)row * NO + tid] = outv;
}

// ---------------------------------------------------------------------------
extern "C" void kernel_launch(void* const* d_in, const int* in_sizes, int n_in,
                              void* d_out, int out_size)
{
    const float* x      = (const float*)d_in[0];
    const float* w_in   = (const float*)d_in[1];
    const float* b_in   = (const float*)d_in[2];
    const float* pos    = (const float*)d_in[3];
    const float* ln1_g  = (const float*)d_in[4];
    const float* ln1_b  = (const float*)d_in[5];
    const float* qkv_w  = (const float*)d_in[6];
    const float* qkv_b  = (const float*)d_in[7];
    const float* proj_w = (const float*)d_in[8];
    const float* proj_b = (const float*)d_in[9];
    const float* ln2_g  = (const float*)d_in[10];
    const float* ln2_b  = (const float*)d_in[11];
    const float* ff1_w  = (const float*)d_in[12];
    const float* ff1_b  = (const float*)d_in[13];
    const float* ff2_w  = (const float*)d_in[14];
    const float* ff2_b  = (const float*)d_in[15];
    const float* lnf_g  = (const float*)d_in[16];
    const float* lnf_b  = (const float*)d_in[17];
    const float* out1_w = (const float*)d_in[18];
    const float* out1_b = (const float*)d_in[19];
    const float* out2_w = (const float*)d_in[20];
    const float* out2_b = (const float*)d_in[21];
    const float* codebooks    = (const float*)d_in[22];
    const float* layer_scales = (const float*)d_in[23];

    float *h, *last, *z1, *z;
    __half *wf, *af, *ff, *xf, *qkvh;
    cudaGetSymbolAddress((void**)&h,    g_h);
    cudaGetSymbolAddress((void**)&last, g_last);
    cudaGetSymbolAddress((void**)&z1,   g_z1);
    cudaGetSymbolAddress((void**)&z,    g_z);
    cudaGetSymbolAddress((void**)&wf,   g_wf);
    cudaGetSymbolAddress((void**)&af,   g_af);
    cudaGetSymbolAddress((void**)&ff,   g_ff);
    cudaGetSymbolAddress((void**)&xf,   g_xf);
    cudaGetSymbolAddress((void**)&qkvh, g_qkvh);

    cudaFuncSetAttribute(gemm_mma<0>, cudaFuncAttributeMaxDynamicSharedMemorySize, GSMEM);
    cudaFuncSetAttribute(gemm_mma<1>, cudaFuncAttributeMaxDynamicSharedMemorySize, GSMEM);
    cudaFuncSetAttribute(gemm_mma<2>, cudaFuncAttributeMaxDynamicSharedMemorySize, GSMEM);
    cudaFuncSetAttribute(gemm_mma<3>, cudaFuncAttributeMaxDynamicSharedMemorySize, GSMEM);
    cudaFuncSetAttribute(gemm_mma<4>, cudaFuncAttributeMaxDynamicSharedMemorySize, GSMEM);

    const dim3 thr(256);
    const dim3 tthr(32, 8);

    // ---- conversions ----
    xcvt<<<(NTOK * NC + 255) / 256, thr>>>(x, xf, NTOK * NC);
    tcvt<<<dim3(ND/32, NC/32), tthr>>>(w_in, wf + OFF_WIN, NC, ND);
    for (int l = 0; l < NL; l++) {
        tcvt<<<dim3(3*ND/32, ND/32), tthr>>>(qkv_w + (size_t)l*QKV_SZ,
            wf + OFF_QKV + (size_t)l*QKV_SZ, ND, 3*ND);
        tcvt<<<dim3(ND/32, ND/32), tthr>>>(proj_w + (size_t)l*PROJ_SZ,
            wf + OFF_PROJ + (size_t)l*PROJ_SZ, ND, ND);
        tcvt<<<dim3(NFF/32, ND/32), tthr>>>(ff1_w + (size_t)l*FF1_SZ,
            wf + OFF_FF1 + (size_t)l*FF1_SZ, ND, NFF);
        tcvt<<<dim3(ND/32, NFF/32), tthr>>>(ff2_w + (size_t)l*FF2_SZ,
            wf + OFF_FF2 + (size_t)l*FF2_SZ, NFF, ND);
    }

    // ---- h = x @ w_in + b_in + pos ----
    gemm_mma<1><<<dim3(ND/128, NTOK/128), thr, GSMEM>>>(
        xf, wf + OFF_WIN, b_in, pos, h, nullptr, NTOK, ND, NC);

    for (int l = 0; l < NL; l++) {
        ln_kernel<1><<<NTOK, thr>>>(h, ln1_g + (size_t)l*ND, ln1_b + (size_t)l*ND,
                                    nullptr, af, ND);
        gemm_mma<4><<<dim3(3*ND/128, NTOK/128), thr, GSMEM>>>(
            af, wf + OFF_QKV + (size_t)l*QKV_SZ,
            qkv_b + (size_t)l*3*ND, nullptr, nullptr, qkvh, NTOK, 3*ND, ND);
        attn_mma<<<dim3(NT/64, NH, NB), 128>>>(qkvh, af);
        gemm_mma<3><<<dim3(ND/128, NTOK/128), thr, GSMEM>>>(
            af, wf + OFF_PROJ + (size_t)l*PROJ_SZ,
            proj_b + (size_t)l*ND, h, h, nullptr, NTOK, ND, ND);
        ln_kernel<1><<<NTOK, thr>>>(h, ln2_g + (size_t)l*ND, ln2_b + (size_t)l*ND,
                                    nullptr, af, ND);
        gemm_mma<2><<<dim3(NFF/128, NTOK/128), thr, GSMEM>>>(
            af, wf + OFF_FF1 + (size_t)l*FF1_SZ,
            ff1_b + (size_t)l*NFF, nullptr, nullptr, ff, NTOK, NFF, ND);
        gemm_mma<3><<<dim3(ND/128, NTOK/128), thr, GSMEM>>>(
            ff, wf + OFF_FF2 + (size_t)l*FF2_SZ,
            ff2_b + (size_t)l*ND, h, h, nullptr, NTOK, ND, NFF);
    }

    // ---- head ----
    ln_kernel<0><<<NB, thr>>>(h + (size_t)(NT - 1) * ND, lnf_g, lnf_b,
                              last, nullptr, (size_t)NT * ND);
    small_gemm<<<NB, thr>>>(last, out1_w, out1_b, z1, ND, ND, 1);
    small_gemm<<<NB, thr>>>(z1, out2_w, out2_b, z, ND, NO, 0);
    rvq_kernel<<<NB, thr>>>(z, codebooks, layer_scales, (float*)d_out);
}